// round 13
// baseline (speedup 1.0000x reference)
#include <cuda_runtime.h>
#include <cuda_bf16.h>
#include <cuda_fp16.h>
#include <cstdint>

#define S_LEN 4096
#define E_DIM 1024
#define H_NUM 16
#define HD    64
#define WSZ   512
#define NTILE 12
#define LOG2E 1.4426950408889634f

// Scratch (allocation-free rule: __device__ globals). All fp16 planes.
#define PLANE (H_NUM * S_LEN * HD)
__device__ __half g_qh[PLANE], g_ql[PLANE];        // Q * log2(e), fp16 split
__device__ __half g_kh[PLANE], g_kl[PLANE];        // K fp16 split
__device__ __half g_vh[PLANE], g_vl[PLANE];        // V fp16 split
__device__ __half g_x16[4 << 20];                  // x fp16, [s][e]
__device__ __half g_wh[4 << 20], g_wl[4 << 20];    // wq|wk|wv|wo fp16 split, [n][k]
__device__ __half g_a16[4 << 20];                  // attention out fp16, [s][e]

// ---------------------------------------------------------------------------
// helpers
// ---------------------------------------------------------------------------
__device__ __forceinline__ float ex2(float x) {
    float r;
    asm("ex2.approx.f32 %0, %1;" : "=f"(r) : "f"(x));
    return r;
}
__device__ __forceinline__ void ldsm4(uint32_t& r0, uint32_t& r1, uint32_t& r2,
                                      uint32_t& r3, uint32_t addr) {
    asm volatile("ldmatrix.sync.aligned.m8n8.x4.shared.b16 {%0,%1,%2,%3}, [%4];"
                 : "=r"(r0), "=r"(r1), "=r"(r2), "=r"(r3) : "r"(addr));
}
__device__ __forceinline__ void ldsm4t(uint32_t& r0, uint32_t& r1, uint32_t& r2,
                                       uint32_t& r3, uint32_t addr) {
    asm volatile("ldmatrix.sync.aligned.m8n8.x4.trans.shared.b16 {%0,%1,%2,%3}, [%4];"
                 : "=r"(r0), "=r"(r1), "=r"(r2), "=r"(r3) : "r"(addr));
}
__device__ __forceinline__ void mma_f16(float c[4],
                                        uint32_t a0, uint32_t a1, uint32_t a2, uint32_t a3,
                                        uint32_t b0, uint32_t b1) {
    asm volatile(
        "mma.sync.aligned.m16n8k16.row.col.f32.f16.f16.f32 "
        "{%0,%1,%2,%3},{%4,%5,%6,%7},{%8,%9},{%0,%1,%2,%3};"
        : "+f"(c[0]), "+f"(c[1]), "+f"(c[2]), "+f"(c[3])
        : "r"(a0), "r"(a1), "r"(a2), "r"(a3), "r"(b0), "r"(b1));
}
__device__ __forceinline__ uint32_t pack_h2(float x0, float x1) {
    uint32_t r;
    asm("cvt.rn.f16x2.f32 %0, %1, %2;" : "=r"(r) : "f"(x1), "f"(x0));
    return r;
}
__device__ __forceinline__ void split2h(float x0, float x1, uint32_t& h, uint32_t& l) {
    h = pack_h2(x0, x1);
    __half2 hv = *reinterpret_cast<__half2*>(&h);
    l = pack_h2(x0 - __half2float(hv.x), x1 - __half2float(hv.y));
}
__device__ __forceinline__ void cp16(uint32_t s, const void* g) {
    asm volatile("cp.async.cg.shared.global [%0], [%1], 16;" :: "r"(s), "l"(g));
}

// ---------------------------------------------------------------------------
// Presplit: x -> fp16 single plane; wq|wk|wv|wo -> fp16 hi/lo planes.
// ---------------------------------------------------------------------------
__global__ __launch_bounds__(256)
void presplit_kernel(const float4* __restrict__ x,  const float4* __restrict__ wq,
                     const float4* __restrict__ wk, const float4* __restrict__ wv,
                     const float4* __restrict__ wo)
{
    int i = blockIdx.x * 256 + threadIdx.x;          // 2M float4
    if (i < (1 << 20)) {
        float4 v = x[i];
        ((uint2*)g_x16)[i] = make_uint2(pack_h2(v.x, v.y), pack_h2(v.z, v.w));
    } else {
        int t = i - (1 << 20);
        int ws = t >> 18;
        int j = t & ((1 << 18) - 1);
        const float4* src = (ws == 0) ? wq : (ws == 1) ? wk : (ws == 2) ? wv : wo;
        float4 v = src[j];
        uint32_t h01, l01, h23, l23;
        split2h(v.x, v.y, h01, l01);
        split2h(v.z, v.w, h23, l23);
        size_t o = ((size_t)ws << 18) + j;
        ((uint2*)g_wh)[o] = make_uint2(h01, h23);
        ((uint2*)g_wl)[o] = make_uint2(l01, l23);
    }
}

// ---------------------------------------------------------------------------
// fp16 2-pass GEMM core: D = A·Bh^T + A·Bl^T over K=1024.
// CTA 128x128, BK=32, 3-stage cp.async ring, fill-BEFORE-compute (race-free:
// fill(c+2) targets stage (c-1)%3 whose readers all passed the top sync),
// one __syncthreads per iter, 32 iters. 8 warps (2m x 4n), warp tile 64x32.
// ---------------------------------------------------------------------------
#define GST  30720   // bytes per stage (A | Bh | Bl, 10240B each)
struct GemmAcc { float a[4][4][4]; };

__device__ __forceinline__ void gemm_core(const __half* __restrict__ A,
                                          const __half* __restrict__ Bh,
                                          const __half* __restrict__ Bl,
                                          int m0, int n0, char* smc, GemmAcc& G)
{
    const uint32_t smu = (uint32_t)__cvta_generic_to_shared(smc);
    const int tid  = threadIdx.x;
    const int warp = tid >> 5, lane = tid & 31;
    const int wm = warp >> 2, wn = warp & 3;

#pragma unroll
    for (int i = 0; i < 4; i++)
#pragma unroll
        for (int j = 0; j < 4; j++)
#pragma unroll
            for (int r = 0; r < 4; r++) G.a[i][j][r] = 0.f;

    const uint32_t aoff = (wm * 64 + (lane & 7) + ((lane >> 3) & 1) * 8) * 80
                        + (lane >> 4) * 16;
    const uint32_t boff = (wn * 32 + (lane & 7) + ((lane >> 3) & 1) * 8) * 80
                        + (lane >> 4) * 16;

    auto fill = [&](int c) {
        int st = c % 3, c0 = c * 32;
        uint32_t sb = smu + (uint32_t)st * GST;
#pragma unroll
        for (int u = 0; u < 2; u++) {
            int f = tid + u * 256;           // 512 cp16 per plane
            int row = f >> 2, g4 = f & 3;
            uint32_t so = row * 80 + g4 * 16;
            size_t gs = (size_t)row * E_DIM + c0 + g4 * 8;
            cp16(sb + so,          A  + (size_t)m0 * E_DIM + gs);
            cp16(sb + 10240 + so,  Bh + (size_t)n0 * E_DIM + gs);
            cp16(sb + 20480 + so,  Bl + (size_t)n0 * E_DIM + gs);
        }
    };
    fill(0);
    asm volatile("cp.async.commit_group;" ::: "memory");
    fill(1);
    asm volatile("cp.async.commit_group;" ::: "memory");

    for (int c = 0; c < 32; c++) {
        asm volatile("cp.async.wait_group 1;" ::: "memory");   // chunk c resident
        __syncthreads();                                       // readers of (c-1)%3 done
        if (c + 2 < 32) fill(c + 2);                           // targets (c-1)%3 — safe
        asm volatile("cp.async.commit_group;" ::: "memory");

        const uint32_t sb = smu + (uint32_t)(c % 3) * GST;
#pragma unroll
        for (int kk = 0; kk < 2; kk++) {
            uint32_t a[4][4], bh[2][4], bl[2][4];
#pragma unroll
            for (int i = 0; i < 4; i++)
                ldsm4(a[i][0], a[i][1], a[i][2], a[i][3],
                      sb + aoff + (uint32_t)(i * 16 * 80 + kk * 32));
#pragma unroll
            for (int p = 0; p < 2; p++) {
                ldsm4(bh[p][0], bh[p][1], bh[p][2], bh[p][3],
                      sb + 10240 + boff + (uint32_t)(p * 16 * 80 + kk * 32));
                ldsm4(bl[p][0], bl[p][1], bl[p][2], bl[p][3],
                      sb + 20480 + boff + (uint32_t)(p * 16 * 80 + kk * 32));
            }
#pragma unroll
            for (int i = 0; i < 4; i++)
#pragma unroll
                for (int p = 0; p < 2; p++) {
                    mma_f16(G.a[i][2*p],   a[i][0], a[i][1], a[i][2], a[i][3],
                            bh[p][0], bh[p][2]);
                    mma_f16(G.a[i][2*p+1], a[i][0], a[i][1], a[i][2], a[i][3],
                            bh[p][1], bh[p][3]);
                    mma_f16(G.a[i][2*p],   a[i][0], a[i][1], a[i][2], a[i][3],
                            bl[p][0], bl[p][2]);
                    mma_f16(G.a[i][2*p+1], a[i][0], a[i][1], a[i][2], a[i][3],
                            bl[p][1], bl[p][3]);
                }
        }
    }
}

// Fused QKV projections: gridDim.z selects Q/K/V.
__global__ __launch_bounds__(256, 2)
void gemm_qkv_kernel(const float* __restrict__ bq, const float* __restrict__ bk,
                     const float* __restrict__ bv)
{
    extern __shared__ char smc[];
    const int z = blockIdx.z;
    const int m0 = blockIdx.y * 128, n0 = blockIdx.x * 128;
    const __half* Bh = g_wh + ((size_t)z << 20);
    const __half* Bl = g_wl + ((size_t)z << 20);
    GemmAcc G;
    gemm_core(g_x16, Bh, Bl, m0, n0, smc, G);

    const float* bias = (z == 0) ? bq : (z == 1) ? bk : bv;
    const int warp = threadIdx.x >> 5, lane = threadIdx.x & 31;
    const int wm = warp >> 2, wn = warp & 3;
#pragma unroll
    for (int i = 0; i < 4; i++) {
#pragma unroll
        for (int j = 0; j < 4; j++) {
            int row = m0 + wm * 64 + i * 16 + (lane >> 2);
            int col = n0 + wn * 32 + j * 8 + (lane & 3) * 2;
#pragma unroll
            for (int rp = 0; rp < 2; rp++) {
                int rr = row + rp * 8;
                float v0 = G.a[i][j][rp * 2 + 0] + bias[col];
                float v1 = G.a[i][j][rp * 2 + 1] + bias[col + 1];
                int hh = col >> 6, dd = col & 63;
                size_t off = ((size_t)hh * S_LEN + rr) * HD + dd;
                uint32_t hp, lp;
                if (z == 0) {
                    split2h(v0 * LOG2E, v1 * LOG2E, hp, lp);
                    *(uint32_t*)(g_qh + off) = hp;
                    *(uint32_t*)(g_ql + off) = lp;
                } else if (z == 1) {
                    split2h(v0, v1, hp, lp);
                    *(uint32_t*)(g_kh + off) = hp;
                    *(uint32_t*)(g_kl + off) = lp;
                } else {
                    split2h(v0, v1, hp, lp);
                    *(uint32_t*)(g_vh + off) = hp;
                    *(uint32_t*)(g_vl + off) = lp;
                }
            }
        }
    }
}

// Output GEMM: out = att @ wo^T + bo (fp32 [s][e]).
__global__ __launch_bounds__(256, 2)
void gemm_out_kernel(const float* __restrict__ bo, float* __restrict__ dst)
{
    extern __shared__ char smc[];
    const int m0 = blockIdx.y * 128, n0 = blockIdx.x * 128;
    GemmAcc G;
    gemm_core(g_a16, g_wh + (3ull << 20), g_wl + (3ull << 20), m0, n0, smc, G);

    const int warp = threadIdx.x >> 5, lane = threadIdx.x & 31;
    const int wm = warp >> 2, wn = warp & 3;
#pragma unroll
    for (int i = 0; i < 4; i++) {
#pragma unroll
        for (int j = 0; j < 4; j++) {
            int row = m0 + wm * 64 + i * 16 + (lane >> 2);
            int col = n0 + wn * 32 + j * 8 + (lane & 3) * 2;
#pragma unroll
            for (int rp = 0; rp < 2; rp++) {
                int rr = row + rp * 8;
                float v0 = G.a[i][j][rp * 2 + 0] + bo[col];
                float v1 = G.a[i][j][rp * 2 + 1] + bo[col + 1];
                *(float2*)(dst + (size_t)rr * E_DIM + col) = make_float2(v0, v1);
            }
        }
    }
}

// ---------------------------------------------------------------------------
// Windowed attention: QK fp16 3-pass (Qh·Kh + Qh·Kl + Ql·Kh — scores ~exact),
// PV fp16 2-pass, log2-domain softmax, cp.async double-buffered K/V,
// closed-form pad tiles, per-warp relevance/mask skipping.
// smem: Qh Ql | 2 x (Kh Kl Vh Vl) = 10 planes x 18432B (row 144B).
// ---------------------------------------------------------------------------
#define RS   72
#define REG  (128 * RS * 2)
__global__ __launch_bounds__(256)
void attn_kernel()
{
    extern __shared__ char smc[];
    const uint32_t smu = (uint32_t)__cvta_generic_to_shared(smc);
    const uint32_t QHI = smu, QLO = smu + REG;

    const int tid  = threadIdx.x;
    const int warp = tid >> 5, lane = tid & 31;
    const int q0   = blockIdx.x * 128;
    const int w    = blockIdx.y;
    const int h    = blockIdx.z;
    const int base = w * WSZ - WSZ;
    const int Q0w  = q0 + warp * 16;

    const uint32_t a_lane = (uint32_t)(((warp * 16 + (lane & 7) + ((lane >> 3) & 1) * 8) * RS
                                        + (lane >> 4) * 8) * 2);
    const uint32_t kb_lane = (uint32_t)((((lane & 7) + ((lane >> 3) & 1) * 8) * RS
                                        + (lane >> 4) * 8) * 2);
    const uint32_t vb_lane = (uint32_t)((((lane & 7) + ((lane >> 4) & 1) * 8) * RS
                                        + ((lane >> 3) & 1) * 8) * 2);

    int tiles[12], nt = 0, npad = 0;
#pragma unroll
    for (int kt = 0; kt < NTILE; kt++) {
        int c0 = kt * 128, t0 = base + c0;
        if (t0 < 0 || t0 >= S_LEN) { npad++; continue; }
        if ((c0 + 127 >= q0) && (c0 <= q0 + 127 + 1024)) tiles[nt++] = kt;
    }

    {
        size_t qoff = ((size_t)h * S_LEN + w * WSZ + q0) * HD;
        for (int f = tid; f < 1024; f += 256) {
            int r = f >> 3, c = f & 7;
            uint32_t so = r * 144 + c * 16;
            size_t go = qoff + (size_t)r * HD + c * 8;
            cp16(QHI + so, g_qh + go);
            cp16(QLO + so, g_ql + go);
        }
    }
    const size_t hoff = (size_t)h * S_LEN * HD;
    auto fetch = [&](int kt, int b) {
        int t0 = base + kt * 128;
        uint32_t sb = smu + (uint32_t)(2 + 4 * b) * REG;
        size_t gb = hoff + (size_t)t0 * HD;
        for (int f = tid; f < 1024; f += 256) {
            int r = f >> 3, c = f & 7;
            uint32_t so = sb + r * 144 + c * 16;
            size_t go = gb + (size_t)r * HD + c * 8;
            cp16(so,           g_kh + go);
            cp16(so + REG,     g_kl + go);
            cp16(so + 2 * REG, g_vh + go);
            cp16(so + 3 * REG, g_vl + go);
        }
    };
    fetch(tiles[0], 0);
    asm volatile("cp.async.commit_group;" ::: "memory");
    if (nt > 1) {
        fetch(tiles[1], 1);
        asm volatile("cp.async.commit_group;" ::: "memory");
    }

    float m0r = -1e30f, m1r = -1e30f, l0r = 0.f, l1r = 0.f;
    float o[8][4];
#pragma unroll
    for (int f = 0; f < 8; f++)
#pragma unroll
        for (int e = 0; e < 4; e++) o[f][e] = 0.f;

    const int r0 = Q0w + (lane >> 2);
    const int r1 = r0 + 8;

    for (int i = 0; i < nt; i++) {
        if (i + 1 < nt) asm volatile("cp.async.wait_group 1;" ::: "memory");
        else            asm volatile("cp.async.wait_group 0;" ::: "memory");
        __syncthreads();

        if (i == 0) {
            // Closed-form pad tiles: s = -sum(q_scaled) (k = v = -1, all valid).
            const __half* qh = (const __half*)smc;
            const __half* ql = (const __half*)(smc + REG);
            int lr0 = warp * 16 + (lane >> 2);
            float qs0 = 0.f, qs1 = 0.f;
#pragma unroll
            for (int d = 0; d < HD; d++) {
                qs0 += __half2float(qh[lr0 * RS + d]) + __half2float(ql[lr0 * RS + d]);
                qs1 += __half2float(qh[(lr0 + 8) * RS + d]) + __half2float(ql[(lr0 + 8) * RS + d]);
            }
            if (npad) {
                float s0 = -qs0, s1 = -qs1;
                float nm0 = fmaxf(m0r, s0), nm1 = fmaxf(m1r, s1);
                float cr0 = ex2(m0r - nm0), cr1 = ex2(m1r - nm1);
                m0r = nm0; m1r = nm1;
                float p0 = ex2(s0 - nm0) * (128.f * npad);
                float p1 = ex2(s1 - nm1) * (128.f * npad);
                l0r = l0r * cr0 + p0;
                l1r = l1r * cr1 + p1;
#pragma unroll
                for (int f = 0; f < 8; f++) {
                    o[f][0] = o[f][0] * cr0 - p0;
                    o[f][1] = o[f][1] * cr0 - p0;
                    o[f][2] = o[f][2] * cr1 - p1;
                    o[f][3] = o[f][3] * cr1 - p1;
                }
            }
        }

        const int kt = tiles[i];
        const int c0 = kt * 128;
        const bool relevant = (c0 + 127 >= Q0w) && (c0 <= Q0w + 1039);

        if (relevant) {
            const uint32_t BB  = smu + (uint32_t)(2 + 4 * (i & 1)) * REG;
            const uint32_t KHI = BB, KLO = BB + REG, VHI = BB + 2 * REG, VLO = BB + 3 * REG;

            // ---- S = Q K^T (fp16 3-pass: Qh·Kh + Qh·Kl + Ql·Kh) ----
            float sS[16][4];
#pragma unroll
            for (int f = 0; f < 16; f++)
#pragma unroll
                for (int e = 0; e < 4; e++) sS[f][e] = 0.f;

#pragma unroll
            for (int s = 0; s < 4; s++) {
                uint32_t ah0, ah1, ah2, ah3, al0, al1, al2, al3;
                ldsm4(ah0, ah1, ah2, ah3, QHI + a_lane + s * 32);
                ldsm4(al0, al1, al2, al3, QLO + a_lane + s * 32);
#pragma unroll
                for (int p = 0; p < 8; p++) {
                    uint32_t bh0, bh1, bh2, bh3, bl0, bl1, bl2, bl3;
                    ldsm4(bh0, bh1, bh2, bh3, KHI + kb_lane + p * 2304 + s * 32);
                    ldsm4(bl0, bl1, bl2, bl3, KLO + kb_lane + p * 2304 + s * 32);
                    mma_f16(sS[2*p],   ah0, ah1, ah2, ah3, bh0, bh2);
                    mma_f16(sS[2*p+1], ah0, ah1, ah2, ah3, bh1, bh3);
                    mma_f16(sS[2*p],   ah0, ah1, ah2, ah3, bl0, bl2);
                    mma_f16(sS[2*p+1], ah0, ah1, ah2, ah3, bl1, bl3);
                    mma_f16(sS[2*p],   al0, al1, al2, al3, bh0, bh2);
                    mma_f16(sS[2*p+1], al0, al1, al2, al3, bh1, bh3);
                }
            }

            const bool needmask = !((c0 >= Q0w + 15) && (c0 + 127 <= Q0w + 1024));
            if (needmask) {
#pragma unroll
                for (int f = 0; f < 16; f++) {
                    int c = c0 + f * 8 + (lane & 3) * 2;
#pragma unroll
                    for (int e = 0; e < 2; e++) {
                        int cc = c + e;
                        if (!(cc >= r0 && cc <= r0 + 1024)) sS[f][e]     = -1e30f;
                        if (!(cc >= r1 && cc <= r1 + 1024)) sS[f][2 + e] = -1e30f;
                    }
                }
            }

            float tm0 = -1e30f, tm1 = -1e30f;
#pragma unroll
            for (int f = 0; f < 16; f++) {
                tm0 = fmaxf(tm0, fmaxf(sS[f][0], sS[f][1]));
                tm1 = fmaxf(tm1, fmaxf(sS[f][2], sS[f][3]));
            }
            tm0 = fmaxf(tm0, __shfl_xor_sync(0xffffffffu, tm0, 1));
            tm0 = fmaxf(tm0, __shfl_xor_sync(0xffffffffu, tm0, 2));
            tm1 = fmaxf(tm1, __shfl_xor_sync(0xffffffffu, tm1, 1));
            tm1 = fmaxf(tm1, __shfl_xor_sync(0xffffffffu, tm1, 2));
            float nm0 = fmaxf(m0r, tm0), nm1 = fmaxf(m1r, tm1);
            float cr0 = ex2(m0r - nm0), cr1 = ex2(m1r - nm1);
            m0r = nm0; m1r = nm1;
#pragma unroll
            for (int f = 0; f < 8; f++) {
                o[f][0] *= cr0; o[f][1] *= cr0;
                o[f][2] *= cr1; o[f][3] *= cr1;
            }
            float la0 = 0.f, la1 = 0.f;

            // ---- P V (exp2 fused, fp16 2-pass: P·Vh + P·Vl) ----
#pragma unroll
            for (int s2 = 0; s2 < 8; s2++) {
                int f0 = 2 * s2, f1 = f0 + 1;
                float p00 = ex2(sS[f0][0] - m0r), p01 = ex2(sS[f0][1] - m0r);
                float p02 = ex2(sS[f0][2] - m1r), p03 = ex2(sS[f0][3] - m1r);
                float p10 = ex2(sS[f1][0] - m0r), p11 = ex2(sS[f1][1] - m0r);
                float p12 = ex2(sS[f1][2] - m1r), p13 = ex2(sS[f1][3] - m1r);
                la0 += p00 + p01 + p10 + p11;
                la1 += p02 + p03 + p12 + p13;
                uint32_t ah0 = pack_h2(p00, p01);
                uint32_t ah1 = pack_h2(p02, p03);
                uint32_t ah2 = pack_h2(p10, p11);
                uint32_t ah3 = pack_h2(p12, p13);
#pragma unroll
                for (int q = 0; q < 4; q++) {
                    uint32_t bh0, bh1, bh2, bh3, bl0, bl1, bl2, bl3;
                    ldsm4t(bh0, bh1, bh2, bh3, VHI + vb_lane + s2 * 2304 + q * 32);
                    ldsm4t(bl0, bl1, bl2, bl3, VLO + vb_lane + s2 * 2304 + q * 32);
                    mma_f16(o[2*q],   ah0, ah1, ah2, ah3, bh0, bh2);
                    mma_f16(o[2*q+1], ah0, ah1, ah2, ah3, bh1, bh3);
                    mma_f16(o[2*q],   ah0, ah1, ah2, ah3, bl0, bl2);
                    mma_f16(o[2*q+1], ah0, ah1, ah2, ah3, bl1, bl3);
                }
            }
            la0 += __shfl_xor_sync(0xffffffffu, la0, 1);
            la0 += __shfl_xor_sync(0xffffffffu, la0, 2);
            la1 += __shfl_xor_sync(0xffffffffu, la1, 1);
            la1 += __shfl_xor_sync(0xffffffffu, la1, 2);
            l0r = l0r * cr0 + la0;
            l1r = l1r * cr1 + la1;
        }

        __syncthreads();
        if (i + 2 < nt) {
            fetch(tiles[i + 2], i & 1);
            asm volatile("cp.async.commit_group;" ::: "memory");
        }
    }

    // normalize + store att as single fp16 plane [s][e]
    const float i0 = 1.f / l0r, i1 = 1.f / l1r;
    const int sg0 = w * WSZ + q0 + warp * 16 + (lane >> 2);
    const int e0  = h * HD + (lane & 3) * 2;
    size_t o0 = (size_t)sg0 * E_DIM + e0;
    size_t o1 = o0 + 8 * E_DIM;
#pragma unroll
    for (int f = 0; f < 8; f++) {
        *(uint32_t*)(g_a16 + o0 + f * 8) = pack_h2(o[f][0] * i0, o[f][1] * i0);
        *(uint32_t*)(g_a16 + o1 + f * 8) = pack_h2(o[f][2] * i1, o[f][3] * i1);
    }
}

// ---------------------------------------------------------------------------
extern "C" void kernel_launch(void* const* d_in, const int* in_sizes, int n_in,
                              void* d_out, int out_size)
{
    const float* x  = (const float*)d_in[0];
    const float* wq = (const float*)d_in[1];
    const float* bq = (const float*)d_in[2];
    const float* wk = (const float*)d_in[3];
    const float* bk = (const float*)d_in[4];
    const float* wv = (const float*)d_in[5];
    const float* bv = (const float*)d_in[6];
    const float* wo = (const float*)d_in[7];
    const float* bo = (const float*)d_in[8];
    float* out = (float*)d_out;

    const int gsm = 3 * GST;           // 92160
    cudaFuncSetAttribute(gemm_qkv_kernel, cudaFuncAttributeMaxDynamicSharedMemorySize, gsm);
    cudaFuncSetAttribute(gemm_out_kernel, cudaFuncAttributeMaxDynamicSharedMemorySize, gsm);
    const int asm_b = 10 * REG;        // 184320
    cudaFuncSetAttribute(attn_kernel, cudaFuncAttributeMaxDynamicSharedMemorySize, asm_b);

    presplit_kernel<<<8192, 256>>>((const float4*)x, (const float4*)wq, (const float4*)wk,
                                   (const float4*)wv, (const float4*)wo);

    dim3 gq(E_DIM / 128, S_LEN / 128, 3);
    gemm_qkv_kernel<<<gq, 256, gsm>>>(bq, bk, bv);

    dim3 ga(4, 8, 16);
    attn_kernel<<<ga, 256, asm_b>>>();

    dim3 gg(E_DIM / 128, S_LEN / 128);
    gemm_out_kernel<<<gg, 256, gsm>>>(bo, out);
}

// round 14
// speedup vs baseline: 1.0206x; 1.0206x over previous
#include <cuda_runtime.h>
#include <cuda_bf16.h>
#include <cuda_fp16.h>
#include <cstdint>

#define S_LEN 4096
#define E_DIM 1024
#define H_NUM 16
#define HD    64
#define WSZ   512
#define NTILE 12
#define LOG2E 1.4426950408889634f

// Scratch (allocation-free rule: __device__ globals). fp16 planes.
#define PLANE (H_NUM * S_LEN * HD)
__device__ __half g_qh[PLANE], g_ql[PLANE];        // Q * log2(e), fp16 split
__device__ __half g_kh[PLANE], g_kl[PLANE];        // K fp16 split
__device__ __half g_vh[PLANE];                     // V fp16 single plane
__device__ __half g_x16[4 << 20];                  // x fp16, [s][e]
__device__ __half g_wh[4 << 20], g_wl[4 << 20];    // wq|wk|wv|wo fp16 split, [n][k]
__device__ __half g_a16[4 << 20];                  // attention out fp16, [s][e]

// ---------------------------------------------------------------------------
// helpers
// ---------------------------------------------------------------------------
__device__ __forceinline__ float ex2(float x) {
    float r;
    asm("ex2.approx.f32 %0, %1;" : "=f"(r) : "f"(x));
    return r;
}
__device__ __forceinline__ void ldsm4(uint32_t& r0, uint32_t& r1, uint32_t& r2,
                                      uint32_t& r3, uint32_t addr) {
    asm volatile("ldmatrix.sync.aligned.m8n8.x4.shared.b16 {%0,%1,%2,%3}, [%4];"
                 : "=r"(r0), "=r"(r1), "=r"(r2), "=r"(r3) : "r"(addr));
}
__device__ __forceinline__ void ldsm4t(uint32_t& r0, uint32_t& r1, uint32_t& r2,
                                       uint32_t& r3, uint32_t addr) {
    asm volatile("ldmatrix.sync.aligned.m8n8.x4.trans.shared.b16 {%0,%1,%2,%3}, [%4];"
                 : "=r"(r0), "=r"(r1), "=r"(r2), "=r"(r3) : "r"(addr));
}
__device__ __forceinline__ void mma_f16(float c[4],
                                        uint32_t a0, uint32_t a1, uint32_t a2, uint32_t a3,
                                        uint32_t b0, uint32_t b1) {
    asm volatile(
        "mma.sync.aligned.m16n8k16.row.col.f32.f16.f16.f32 "
        "{%0,%1,%2,%3},{%4,%5,%6,%7},{%8,%9},{%0,%1,%2,%3};"
        : "+f"(c[0]), "+f"(c[1]), "+f"(c[2]), "+f"(c[3])
        : "r"(a0), "r"(a1), "r"(a2), "r"(a3), "r"(b0), "r"(b1));
}
__device__ __forceinline__ uint32_t pack_h2(float x0, float x1) {
    uint32_t r;
    asm("cvt.rn.f16x2.f32 %0, %1, %2;" : "=r"(r) : "f"(x1), "f"(x0));
    return r;
}
__device__ __forceinline__ void split2h(float x0, float x1, uint32_t& h, uint32_t& l) {
    h = pack_h2(x0, x1);
    __half2 hv = *reinterpret_cast<__half2*>(&h);
    l = pack_h2(x0 - __half2float(hv.x), x1 - __half2float(hv.y));
}
__device__ __forceinline__ void cp16(uint32_t s, const void* g) {
    asm volatile("cp.async.cg.shared.global [%0], [%1], 16;" :: "r"(s), "l"(g));
}

// ---------------------------------------------------------------------------
// Presplit: x -> fp16 single plane; wq|wk|wv|wo -> fp16 hi/lo planes.
// ---------------------------------------------------------------------------
__global__ __launch_bounds__(256)
void presplit_kernel(const float4* __restrict__ x,  const float4* __restrict__ wq,
                     const float4* __restrict__ wk, const float4* __restrict__ wv,
                     const float4* __restrict__ wo)
{
    int i = blockIdx.x * 256 + threadIdx.x;          // 2M float4
    if (i < (1 << 20)) {
        float4 v = x[i];
        ((uint2*)g_x16)[i] = make_uint2(pack_h2(v.x, v.y), pack_h2(v.z, v.w));
    } else {
        int t = i - (1 << 20);
        int ws = t >> 18;
        int j = t & ((1 << 18) - 1);
        const float4* src = (ws == 0) ? wq : (ws == 1) ? wk : (ws == 2) ? wv : wo;
        float4 v = src[j];
        uint32_t h01, l01, h23, l23;
        split2h(v.x, v.y, h01, l01);
        split2h(v.z, v.w, h23, l23);
        size_t o = ((size_t)ws << 18) + j;
        ((uint2*)g_wh)[o] = make_uint2(h01, h23);
        ((uint2*)g_wl)[o] = make_uint2(l01, l23);
    }
}

// ---------------------------------------------------------------------------
// fp16 2-pass GEMM core: D = A·Bh^T + A·Bl^T over K=1024.
// R9 schedule: CTA 128x128, BK=16, 4-stage cp.async ring, fill(c+3) AFTER
// compute (race-free: targets stage (c-1)&3 released by this iter's top sync),
// one __syncthreads/iter, 64 iters. 8 warps (2m x 4n), warp tile 64x32.
// Row stride 48B (banks {0,12,24,4,16,28,8,20} -> conflict-free ldsm).
// ---------------------------------------------------------------------------
#define GPL  6144    // bytes per plane per stage (128 rows x 48B)
#define GST  (3 * GPL)   // 18432: A | Bh | Bl
struct GemmAcc { float a[4][4][4]; };

__device__ __forceinline__ void gemm_core(const __half* __restrict__ A,
                                          const __half* __restrict__ Bh,
                                          const __half* __restrict__ Bl,
                                          int m0, int n0, char* smc, GemmAcc& G)
{
    const uint32_t smu = (uint32_t)__cvta_generic_to_shared(smc);
    const int tid  = threadIdx.x;
    const int warp = tid >> 5, lane = tid & 31;
    const int wm = warp >> 2, wn = warp & 3;

#pragma unroll
    for (int i = 0; i < 4; i++)
#pragma unroll
        for (int j = 0; j < 4; j++)
#pragma unroll
            for (int r = 0; r < 4; r++) G.a[i][j][r] = 0.f;

    const uint32_t aoff = (wm * 64 + (lane & 7) + ((lane >> 3) & 1) * 8) * 48
                        + (lane >> 4) * 16;
    const uint32_t boff = GPL + (wn * 32 + (lane & 7) + ((lane >> 3) & 1) * 8) * 48
                        + (lane >> 4) * 16;

    auto fill = [&](int c) {
        int st = c & 3, k0 = c * 16;
        uint32_t sb = smu + (uint32_t)st * GST;
#pragma unroll
        for (int u = 0; u < 3; u++) {
            int f = tid + u * 256;               // 768 cp16 total (256/plane)
            int pl = f >> 8, idx = f & 255;
            int row = idx >> 1, g8 = idx & 1;
            const __half* sp = (pl == 0) ? (A + (size_t)m0 * E_DIM)
                             : (pl == 1) ? (Bh + (size_t)n0 * E_DIM)
                                         : (Bl + (size_t)n0 * E_DIM);
            cp16(sb + (uint32_t)pl * GPL + row * 48 + g8 * 16,
                 sp + (size_t)row * E_DIM + k0 + g8 * 8);
        }
    };
    fill(0);
    asm volatile("cp.async.commit_group;" ::: "memory");
    fill(1);
    asm volatile("cp.async.commit_group;" ::: "memory");
    fill(2);
    asm volatile("cp.async.commit_group;" ::: "memory");

    for (int c = 0; c < 64; c++) {
        asm volatile("cp.async.wait_group 2;" ::: "memory");
        __syncthreads();

        const uint32_t sb = smu + (uint32_t)(c & 3) * GST;
        uint32_t a[4][4], bh[2][4], bl[2][4];
#pragma unroll
        for (int i = 0; i < 4; i++)
            ldsm4(a[i][0], a[i][1], a[i][2], a[i][3],
                  sb + aoff + (uint32_t)(i * 16 * 48));
#pragma unroll
        for (int p = 0; p < 2; p++) {
            ldsm4(bh[p][0], bh[p][1], bh[p][2], bh[p][3],
                  sb + boff + (uint32_t)(p * 16 * 48));
            ldsm4(bl[p][0], bl[p][1], bl[p][2], bl[p][3],
                  sb + GPL + boff + (uint32_t)(p * 16 * 48));
        }
#pragma unroll
        for (int i = 0; i < 4; i++)
#pragma unroll
            for (int p = 0; p < 2; p++) {
                mma_f16(G.a[i][2*p],   a[i][0], a[i][1], a[i][2], a[i][3],
                        bh[p][0], bh[p][2]);
                mma_f16(G.a[i][2*p+1], a[i][0], a[i][1], a[i][2], a[i][3],
                        bh[p][1], bh[p][3]);
                mma_f16(G.a[i][2*p],   a[i][0], a[i][1], a[i][2], a[i][3],
                        bl[p][0], bl[p][2]);
                mma_f16(G.a[i][2*p+1], a[i][0], a[i][1], a[i][2], a[i][3],
                        bl[p][1], bl[p][3]);
            }
        // fill into stage (c-1)&3, released by this iteration's top sync
        if (c + 3 < 64) fill(c + 3);
        asm volatile("cp.async.commit_group;" ::: "memory");   // may be empty
    }
}

// Fused QKV projections: gridDim.z selects Q/K/V.
__global__ __launch_bounds__(256, 2)
void gemm_qkv_kernel(const float* __restrict__ bq, const float* __restrict__ bk,
                     const float* __restrict__ bv)
{
    extern __shared__ char smc[];
    const int z = blockIdx.z;
    const int m0 = blockIdx.y * 128, n0 = blockIdx.x * 128;
    const __half* Bh = g_wh + ((size_t)z << 20);
    const __half* Bl = g_wl + ((size_t)z << 20);
    GemmAcc G;
    gemm_core(g_x16, Bh, Bl, m0, n0, smc, G);

    const float* bias = (z == 0) ? bq : (z == 1) ? bk : bv;
    const int warp = threadIdx.x >> 5, lane = threadIdx.x & 31;
    const int wm = warp >> 2, wn = warp & 3;
#pragma unroll
    for (int i = 0; i < 4; i++) {
#pragma unroll
        for (int j = 0; j < 4; j++) {
            int row = m0 + wm * 64 + i * 16 + (lane >> 2);
            int col = n0 + wn * 32 + j * 8 + (lane & 3) * 2;
#pragma unroll
            for (int rp = 0; rp < 2; rp++) {
                int rr = row + rp * 8;
                float v0 = G.a[i][j][rp * 2 + 0] + bias[col];
                float v1 = G.a[i][j][rp * 2 + 1] + bias[col + 1];
                int hh = col >> 6, dd = col & 63;
                size_t off = ((size_t)hh * S_LEN + rr) * HD + dd;
                uint32_t hp, lp;
                if (z == 0) {
                    split2h(v0 * LOG2E, v1 * LOG2E, hp, lp);
                    *(uint32_t*)(g_qh + off) = hp;
                    *(uint32_t*)(g_ql + off) = lp;
                } else if (z == 1) {
                    split2h(v0, v1, hp, lp);
                    *(uint32_t*)(g_kh + off) = hp;
                    *(uint32_t*)(g_kl + off) = lp;
                } else {
                    *(uint32_t*)(g_vh + off) = pack_h2(v0, v1);
                }
            }
        }
    }
}

// Output GEMM: out = att @ wo^T + bo (fp32 [s][e]).
__global__ __launch_bounds__(256, 2)
void gemm_out_kernel(const float* __restrict__ bo, float* __restrict__ dst)
{
    extern __shared__ char smc[];
    const int m0 = blockIdx.y * 128, n0 = blockIdx.x * 128;
    GemmAcc G;
    gemm_core(g_a16, g_wh + (3ull << 20), g_wl + (3ull << 20), m0, n0, smc, G);

    const int warp = threadIdx.x >> 5, lane = threadIdx.x & 31;
    const int wm = warp >> 2, wn = warp & 3;
#pragma unroll
    for (int i = 0; i < 4; i++) {
#pragma unroll
        for (int j = 0; j < 4; j++) {
            int row = m0 + wm * 64 + i * 16 + (lane >> 2);
            int col = n0 + wn * 32 + j * 8 + (lane & 3) * 2;
#pragma unroll
            for (int rp = 0; rp < 2; rp++) {
                int rr = row + rp * 8;
                float v0 = G.a[i][j][rp * 2 + 0] + bo[col];
                float v1 = G.a[i][j][rp * 2 + 1] + bo[col + 1];
                *(float2*)(dst + (size_t)rr * E_DIM + col) = make_float2(v0, v1);
            }
        }
    }
}

// ---------------------------------------------------------------------------
// Windowed attention: QK fp16 3-pass (Qh·Kh + Qh·Kl + Ql·Kh — scores ~exact),
// PV fp16 SINGLE pass (V one plane), log2-domain softmax, cp.async
// double-buffered K/V, closed-form pad tiles, per-warp relevance/mask skip.
// smem: Qh Ql | 2 x (Kh Kl V) = 8 planes x 18432B (row 144B).
// ---------------------------------------------------------------------------
#define RS   72
#define REG  (128 * RS * 2)
__global__ __launch_bounds__(256)
void attn_kernel()
{
    extern __shared__ char smc[];
    const uint32_t smu = (uint32_t)__cvta_generic_to_shared(smc);
    const uint32_t QHI = smu, QLO = smu + REG;

    const int tid  = threadIdx.x;
    const int warp = tid >> 5, lane = tid & 31;
    const int q0   = blockIdx.x * 128;
    const int w    = blockIdx.y;
    const int h    = blockIdx.z;
    const int base = w * WSZ - WSZ;
    const int Q0w  = q0 + warp * 16;

    const uint32_t a_lane = (uint32_t)(((warp * 16 + (lane & 7) + ((lane >> 3) & 1) * 8) * RS
                                        + (lane >> 4) * 8) * 2);
    const uint32_t kb_lane = (uint32_t)((((lane & 7) + ((lane >> 3) & 1) * 8) * RS
                                        + (lane >> 4) * 8) * 2);
    const uint32_t vb_lane = (uint32_t)((((lane & 7) + ((lane >> 4) & 1) * 8) * RS
                                        + ((lane >> 3) & 1) * 8) * 2);

    int tiles[12], nt = 0, npad = 0;
#pragma unroll
    for (int kt = 0; kt < NTILE; kt++) {
        int c0 = kt * 128, t0 = base + c0;
        if (t0 < 0 || t0 >= S_LEN) { npad++; continue; }
        if ((c0 + 127 >= q0) && (c0 <= q0 + 127 + 1024)) tiles[nt++] = kt;
    }

    {
        size_t qoff = ((size_t)h * S_LEN + w * WSZ + q0) * HD;
        for (int f = tid; f < 1024; f += 256) {
            int r = f >> 3, c = f & 7;
            uint32_t so = r * 144 + c * 16;
            size_t go = qoff + (size_t)r * HD + c * 8;
            cp16(QHI + so, g_qh + go);
            cp16(QLO + so, g_ql + go);
        }
    }
    const size_t hoff = (size_t)h * S_LEN * HD;
    auto fetch = [&](int kt, int b) {
        int t0 = base + kt * 128;
        uint32_t sb = smu + (uint32_t)(2 + 3 * b) * REG;
        size_t gb = hoff + (size_t)t0 * HD;
        for (int f = tid; f < 1024; f += 256) {
            int r = f >> 3, c = f & 7;
            uint32_t so = sb + r * 144 + c * 16;
            size_t go = gb + (size_t)r * HD + c * 8;
            cp16(so,           g_kh + go);
            cp16(so + REG,     g_kl + go);
            cp16(so + 2 * REG, g_vh + go);
        }
    };
    fetch(tiles[0], 0);
    asm volatile("cp.async.commit_group;" ::: "memory");
    if (nt > 1) {
        fetch(tiles[1], 1);
        asm volatile("cp.async.commit_group;" ::: "memory");
    }

    float m0r = -1e30f, m1r = -1e30f, l0r = 0.f, l1r = 0.f;
    float o[8][4];
#pragma unroll
    for (int f = 0; f < 8; f++)
#pragma unroll
        for (int e = 0; e < 4; e++) o[f][e] = 0.f;

    const int r0 = Q0w + (lane >> 2);
    const int r1 = r0 + 8;

    for (int i = 0; i < nt; i++) {
        if (i + 1 < nt) asm volatile("cp.async.wait_group 1;" ::: "memory");
        else            asm volatile("cp.async.wait_group 0;" ::: "memory");
        __syncthreads();

        if (i == 0) {
            // Closed-form pad tiles: s = -sum(q_scaled) (k = v = -1, all valid).
            const __half* qh = (const __half*)smc;
            const __half* ql = (const __half*)(smc + REG);
            int lr0 = warp * 16 + (lane >> 2);
            float qs0 = 0.f, qs1 = 0.f;
#pragma unroll
            for (int d = 0; d < HD; d++) {
                qs0 += __half2float(qh[lr0 * RS + d]) + __half2float(ql[lr0 * RS + d]);
                qs1 += __half2float(qh[(lr0 + 8) * RS + d]) + __half2float(ql[(lr0 + 8) * RS + d]);
            }
            if (npad) {
                float s0 = -qs0, s1 = -qs1;
                float nm0 = fmaxf(m0r, s0), nm1 = fmaxf(m1r, s1);
                float cr0 = ex2(m0r - nm0), cr1 = ex2(m1r - nm1);
                m0r = nm0; m1r = nm1;
                float p0 = ex2(s0 - nm0) * (128.f * npad);
                float p1 = ex2(s1 - nm1) * (128.f * npad);
                l0r = l0r * cr0 + p0;
                l1r = l1r * cr1 + p1;
#pragma unroll
                for (int f = 0; f < 8; f++) {
                    o[f][0] = o[f][0] * cr0 - p0;
                    o[f][1] = o[f][1] * cr0 - p0;
                    o[f][2] = o[f][2] * cr1 - p1;
                    o[f][3] = o[f][3] * cr1 - p1;
                }
            }
        }

        const int kt = tiles[i];
        const int c0 = kt * 128;
        const bool relevant = (c0 + 127 >= Q0w) && (c0 <= Q0w + 1039);

        if (relevant) {
            const uint32_t BB  = smu + (uint32_t)(2 + 3 * (i & 1)) * REG;
            const uint32_t KHI = BB, KLO = BB + REG, VHI = BB + 2 * REG;

            // ---- S = Q K^T (fp16 3-pass: Qh·Kh + Qh·Kl + Ql·Kh) ----
            float sS[16][4];
#pragma unroll
            for (int f = 0; f < 16; f++)
#pragma unroll
                for (int e = 0; e < 4; e++) sS[f][e] = 0.f;

#pragma unroll
            for (int s = 0; s < 4; s++) {
                uint32_t ah0, ah1, ah2, ah3, al0, al1, al2, al3;
                ldsm4(ah0, ah1, ah2, ah3, QHI + a_lane + s * 32);
                ldsm4(al0, al1, al2, al3, QLO + a_lane + s * 32);
#pragma unroll
                for (int p = 0; p < 8; p++) {
                    uint32_t bh0, bh1, bh2, bh3, bl0, bl1, bl2, bl3;
                    ldsm4(bh0, bh1, bh2, bh3, KHI + kb_lane + p * 2304 + s * 32);
                    ldsm4(bl0, bl1, bl2, bl3, KLO + kb_lane + p * 2304 + s * 32);
                    mma_f16(sS[2*p],   ah0, ah1, ah2, ah3, bh0, bh2);
                    mma_f16(sS[2*p+1], ah0, ah1, ah2, ah3, bh1, bh3);
                    mma_f16(sS[2*p],   ah0, ah1, ah2, ah3, bl0, bl2);
                    mma_f16(sS[2*p+1], ah0, ah1, ah2, ah3, bl1, bl3);
                    mma_f16(sS[2*p],   al0, al1, al2, al3, bh0, bh2);
                    mma_f16(sS[2*p+1], al0, al1, al2, al3, bh1, bh3);
                }
            }

            const bool needmask = !((c0 >= Q0w + 15) && (c0 + 127 <= Q0w + 1024));
            if (needmask) {
#pragma unroll
                for (int f = 0; f < 16; f++) {
                    int c = c0 + f * 8 + (lane & 3) * 2;
#pragma unroll
                    for (int e = 0; e < 2; e++) {
                        int cc = c + e;
                        if (!(cc >= r0 && cc <= r0 + 1024)) sS[f][e]     = -1e30f;
                        if (!(cc >= r1 && cc <= r1 + 1024)) sS[f][2 + e] = -1e30f;
                    }
                }
            }

            float tm0 = -1e30f, tm1 = -1e30f;
#pragma unroll
            for (int f = 0; f < 16; f++) {
                tm0 = fmaxf(tm0, fmaxf(sS[f][0], sS[f][1]));
                tm1 = fmaxf(tm1, fmaxf(sS[f][2], sS[f][3]));
            }
            tm0 = fmaxf(tm0, __shfl_xor_sync(0xffffffffu, tm0, 1));
            tm0 = fmaxf(tm0, __shfl_xor_sync(0xffffffffu, tm0, 2));
            tm1 = fmaxf(tm1, __shfl_xor_sync(0xffffffffu, tm1, 1));
            tm1 = fmaxf(tm1, __shfl_xor_sync(0xffffffffu, tm1, 2));
            float nm0 = fmaxf(m0r, tm0), nm1 = fmaxf(m1r, tm1);
            float cr0 = ex2(m0r - nm0), cr1 = ex2(m1r - nm1);
            m0r = nm0; m1r = nm1;
#pragma unroll
            for (int f = 0; f < 8; f++) {
                o[f][0] *= cr0; o[f][1] *= cr0;
                o[f][2] *= cr1; o[f][3] *= cr1;
            }
            float la0 = 0.f, la1 = 0.f;

            // ---- P V (exp2 fused, fp16 single pass) ----
#pragma unroll
            for (int s2 = 0; s2 < 8; s2++) {
                int f0 = 2 * s2, f1 = f0 + 1;
                float p00 = ex2(sS[f0][0] - m0r), p01 = ex2(sS[f0][1] - m0r);
                float p02 = ex2(sS[f0][2] - m1r), p03 = ex2(sS[f0][3] - m1r);
                float p10 = ex2(sS[f1][0] - m0r), p11 = ex2(sS[f1][1] - m0r);
                float p12 = ex2(sS[f1][2] - m1r), p13 = ex2(sS[f1][3] - m1r);
                la0 += p00 + p01 + p10 + p11;
                la1 += p02 + p03 + p12 + p13;
                uint32_t ah0 = pack_h2(p00, p01);
                uint32_t ah1 = pack_h2(p02, p03);
                uint32_t ah2 = pack_h2(p10, p11);
                uint32_t ah3 = pack_h2(p12, p13);
#pragma unroll
                for (int q = 0; q < 4; q++) {
                    uint32_t bh0, bh1, bh2, bh3;
                    ldsm4t(bh0, bh1, bh2, bh3, VHI + vb_lane + s2 * 2304 + q * 32);
                    mma_f16(o[2*q],   ah0, ah1, ah2, ah3, bh0, bh2);
                    mma_f16(o[2*q+1], ah0, ah1, ah2, ah3, bh1, bh3);
                }
            }
            la0 += __shfl_xor_sync(0xffffffffu, la0, 1);
            la0 += __shfl_xor_sync(0xffffffffu, la0, 2);
            la1 += __shfl_xor_sync(0xffffffffu, la1, 1);
            la1 += __shfl_xor_sync(0xffffffffu, la1, 2);
            l0r = l0r * cr0 + la0;
            l1r = l1r * cr1 + la1;
        }

        __syncthreads();
        if (i + 2 < nt) {
            fetch(tiles[i + 2], i & 1);
            asm volatile("cp.async.commit_group;" ::: "memory");
        }
    }

    // normalize + store att as single fp16 plane [s][e]
    const float i0 = 1.f / l0r, i1 = 1.f / l1r;
    const int sg0 = w * WSZ + q0 + warp * 16 + (lane >> 2);
    const int e0  = h * HD + (lane & 3) * 2;
    size_t o0 = (size_t)sg0 * E_DIM + e0;
    size_t o1 = o0 + 8 * E_DIM;
#pragma unroll
    for (int f = 0; f < 8; f++) {
        *(uint32_t*)(g_a16 + o0 + f * 8) = pack_h2(o[f][0] * i0, o[f][1] * i0);
        *(uint32_t*)(g_a16 + o1 + f * 8) = pack_h2(o[f][2] * i1, o[f][3] * i1);
    }
}

// ---------------------------------------------------------------------------
extern "C" void kernel_launch(void* const* d_in, const int* in_sizes, int n_in,
                              void* d_out, int out_size)
{
    const float* x  = (const float*)d_in[0];
    const float* wq = (const float*)d_in[1];
    const float* bq = (const float*)d_in[2];
    const float* wk = (const float*)d_in[3];
    const float* bk = (const float*)d_in[4];
    const float* wv = (const float*)d_in[5];
    const float* bv = (const float*)d_in[6];
    const float* wo = (const float*)d_in[7];
    const float* bo = (const float*)d_in[8];
    float* out = (float*)d_out;

    const int gsm = 4 * GST;           // 73728
    cudaFuncSetAttribute(gemm_qkv_kernel, cudaFuncAttributeMaxDynamicSharedMemorySize, gsm);
    cudaFuncSetAttribute(gemm_out_kernel, cudaFuncAttributeMaxDynamicSharedMemorySize, gsm);
    const int asm_b = 8 * REG;         // 147456
    cudaFuncSetAttribute(attn_kernel, cudaFuncAttributeMaxDynamicSharedMemorySize, asm_b);

    presplit_kernel<<<8192, 256>>>((const float4*)x, (const float4*)wq, (const float4*)wk,
                                   (const float4*)wv, (const float4*)wo);

    dim3 gq(E_DIM / 128, S_LEN / 128, 3);
    gemm_qkv_kernel<<<gq, 256, gsm>>>(bq, bk, bv);

    dim3 ga(4, 8, 16);
    attn_kernel<<<ga, 256, asm_b>>>();

    dim3 gg(E_DIM / 128, S_LEN / 128);
    gemm_out_kernel<<<gg, 256, gsm>>>(bo, out);
}

// round 16
// speedup vs baseline: 1.1867x; 1.1627x over previous
#include <cuda_runtime.h>
#include <cuda_bf16.h>
#include <cuda_fp16.h>
#include <cstdint>

#define S_LEN 4096
#define E_DIM 1024
#define H_NUM 16
#define HD    64
#define WSZ   512
#define NTILE 12
#define LOG2E 1.4426950408889634f

// Scratch (allocation-free rule: __device__ globals). fp16 planes.
#define PLANE (H_NUM * S_LEN * HD)
__device__ __half g_qh[PLANE], g_ql[PLANE];        // Q * log2(e), fp16 split
__device__ __half g_kh[PLANE], g_kl[PLANE];        // K fp16 split
__device__ __half g_vh[PLANE];                     // V fp16 single plane
__device__ __half g_x16[4 << 20];                  // x fp16, [s][e]
__device__ __half g_wh[4 << 20], g_wl[4 << 20];    // wq|wk|wv|wo fp16 split, [n][k]
__device__ __half g_a16[4 << 20];                  // attention out fp16, [s][e]

// ---------------------------------------------------------------------------
// helpers
// ---------------------------------------------------------------------------
__device__ __forceinline__ float ex2(float x) {
    float r;
    asm("ex2.approx.f32 %0, %1;" : "=f"(r) : "f"(x));
    return r;
}
__device__ __forceinline__ void ldsm4(uint32_t& r0, uint32_t& r1, uint32_t& r2,
                                      uint32_t& r3, uint32_t addr) {
    asm volatile("ldmatrix.sync.aligned.m8n8.x4.shared.b16 {%0,%1,%2,%3}, [%4];"
                 : "=r"(r0), "=r"(r1), "=r"(r2), "=r"(r3) : "r"(addr));
}
__device__ __forceinline__ void ldsm4t(uint32_t& r0, uint32_t& r1, uint32_t& r2,
                                       uint32_t& r3, uint32_t addr) {
    asm volatile("ldmatrix.sync.aligned.m8n8.x4.trans.shared.b16 {%0,%1,%2,%3}, [%4];"
                 : "=r"(r0), "=r"(r1), "=r"(r2), "=r"(r3) : "r"(addr));
}
__device__ __forceinline__ void mma_f16(float c[4],
                                        uint32_t a0, uint32_t a1, uint32_t a2, uint32_t a3,
                                        uint32_t b0, uint32_t b1) {
    asm volatile(
        "mma.sync.aligned.m16n8k16.row.col.f32.f16.f16.f32 "
        "{%0,%1,%2,%3},{%4,%5,%6,%7},{%8,%9},{%0,%1,%2,%3};"
        : "+f"(c[0]), "+f"(c[1]), "+f"(c[2]), "+f"(c[3])
        : "r"(a0), "r"(a1), "r"(a2), "r"(a3), "r"(b0), "r"(b1));
}
__device__ __forceinline__ uint32_t pack_h2(float x0, float x1) {
    uint32_t r;
    asm("cvt.rn.f16x2.f32 %0, %1, %2;" : "=r"(r) : "f"(x1), "f"(x0));
    return r;
}
__device__ __forceinline__ void split2h(float x0, float x1, uint32_t& h, uint32_t& l) {
    h = pack_h2(x0, x1);
    __half2 hv = *reinterpret_cast<__half2*>(&h);
    l = pack_h2(x0 - __half2float(hv.x), x1 - __half2float(hv.y));
}
__device__ __forceinline__ void cp16(uint32_t s, const void* g) {
    asm volatile("cp.async.cg.shared.global [%0], [%1], 16;" :: "r"(s), "l"(g));
}

// ---------------------------------------------------------------------------
// Presplit: x -> fp16 single plane; wq|wk|wv|wo -> fp16 hi/lo planes.
// ---------------------------------------------------------------------------
__global__ __launch_bounds__(256)
void presplit_kernel(const float4* __restrict__ x,  const float4* __restrict__ wq,
                     const float4* __restrict__ wk, const float4* __restrict__ wv,
                     const float4* __restrict__ wo)
{
    int i = blockIdx.x * 256 + threadIdx.x;          // 2M float4
    if (i < (1 << 20)) {
        float4 v = x[i];
        ((uint2*)g_x16)[i] = make_uint2(pack_h2(v.x, v.y), pack_h2(v.z, v.w));
    } else {
        int t = i - (1 << 20);
        int ws = t >> 18;
        int j = t & ((1 << 18) - 1);
        const float4* src = (ws == 0) ? wq : (ws == 1) ? wk : (ws == 2) ? wv : wo;
        float4 v = src[j];
        uint32_t h01, l01, h23, l23;
        split2h(v.x, v.y, h01, l01);
        split2h(v.z, v.w, h23, l23);
        size_t o = ((size_t)ws << 18) + j;
        ((uint2*)g_wh)[o] = make_uint2(h01, h23);
        ((uint2*)g_wl)[o] = make_uint2(l01, l23);
    }
}

struct GemmAcc { float a[4][4][4]; };

// ---------------------------------------------------------------------------
// 2-pass fp16 GEMM core (for Q/K projections): D = A·Bh^T + A·Bl^T, K=1024.
// R14 schedule: BK=16, 4-stage ring, fill(c+3) AFTER compute, 64 iters.
// Row stride 48B (conflict-free banks {0,12,24,4,16,28,8,20}).
// ---------------------------------------------------------------------------
#define GPL2 6144
#define GST2 (3 * GPL2)   // 18432: A | Bh | Bl

__device__ __forceinline__ void gemm2_core(const __half* __restrict__ A,
                                           const __half* __restrict__ Bh,
                                           const __half* __restrict__ Bl,
                                           int m0, int n0, char* smc, GemmAcc& G)
{
    const uint32_t smu = (uint32_t)__cvta_generic_to_shared(smc);
    const int tid  = threadIdx.x;
    const int warp = tid >> 5, lane = tid & 31;
    const int wm = warp >> 2, wn = warp & 3;

#pragma unroll
    for (int i = 0; i < 4; i++)
#pragma unroll
        for (int j = 0; j < 4; j++)
#pragma unroll
            for (int r = 0; r < 4; r++) G.a[i][j][r] = 0.f;

    const uint32_t aoff = (wm * 64 + (lane & 7) + ((lane >> 3) & 1) * 8) * 48
                        + (lane >> 4) * 16;
    const uint32_t boff = GPL2 + (wn * 32 + (lane & 7) + ((lane >> 3) & 1) * 8) * 48
                        + (lane >> 4) * 16;

    auto fill = [&](int c) {
        int st = c & 3, k0 = c * 16;
        uint32_t sb = smu + (uint32_t)st * GST2;
#pragma unroll
        for (int u = 0; u < 3; u++) {
            int f = tid + u * 256;
            int pl = f >> 8, idx = f & 255;
            int row = idx >> 1, g8 = idx & 1;
            const __half* sp = (pl == 0) ? (A + (size_t)m0 * E_DIM)
                             : (pl == 1) ? (Bh + (size_t)n0 * E_DIM)
                                         : (Bl + (size_t)n0 * E_DIM);
            cp16(sb + (uint32_t)pl * GPL2 + row * 48 + g8 * 16,
                 sp + (size_t)row * E_DIM + k0 + g8 * 8);
        }
    };
    fill(0);
    asm volatile("cp.async.commit_group;" ::: "memory");
    fill(1);
    asm volatile("cp.async.commit_group;" ::: "memory");
    fill(2);
    asm volatile("cp.async.commit_group;" ::: "memory");

    for (int c = 0; c < 64; c++) {
        asm volatile("cp.async.wait_group 2;" ::: "memory");
        __syncthreads();

        const uint32_t sb = smu + (uint32_t)(c & 3) * GST2;
        uint32_t a[4][4], bh[2][4], bl[2][4];
#pragma unroll
        for (int i = 0; i < 4; i++)
            ldsm4(a[i][0], a[i][1], a[i][2], a[i][3],
                  sb + aoff + (uint32_t)(i * 16 * 48));
#pragma unroll
        for (int p = 0; p < 2; p++) {
            ldsm4(bh[p][0], bh[p][1], bh[p][2], bh[p][3],
                  sb + boff + (uint32_t)(p * 16 * 48));
            ldsm4(bl[p][0], bl[p][1], bl[p][2], bl[p][3],
                  sb + GPL2 + boff + (uint32_t)(p * 16 * 48));
        }
#pragma unroll
        for (int i = 0; i < 4; i++)
#pragma unroll
            for (int p = 0; p < 2; p++) {
                mma_f16(G.a[i][2*p],   a[i][0], a[i][1], a[i][2], a[i][3],
                        bh[p][0], bh[p][2]);
                mma_f16(G.a[i][2*p+1], a[i][0], a[i][1], a[i][2], a[i][3],
                        bh[p][1], bh[p][3]);
                mma_f16(G.a[i][2*p],   a[i][0], a[i][1], a[i][2], a[i][3],
                        bl[p][0], bl[p][2]);
                mma_f16(G.a[i][2*p+1], a[i][0], a[i][1], a[i][2], a[i][3],
                        bl[p][1], bl[p][3]);
            }
        if (c + 3 < 64) fill(c + 3);
        asm volatile("cp.async.commit_group;" ::: "memory");
    }
}

// ---------------------------------------------------------------------------
// 1-pass fp16 GEMM core (for V projection + output GEMM): D = A·B^T, K=1024.
// BK=32, 4-stage ring, fill(c+3) AFTER compute, 32 iters.
// Row stride 80B (conflict-free banks {0,20,8,28,16,4,24,12}).
// ---------------------------------------------------------------------------
#define GPL1 10240   // 128 rows x 80B
#define GST1 (2 * GPL1)   // 20480: A | B

__device__ __forceinline__ void gemm1_core(const __half* __restrict__ A,
                                           const __half* __restrict__ B,
                                           int m0, int n0, char* smc, GemmAcc& G)
{
    const uint32_t smu = (uint32_t)__cvta_generic_to_shared(smc);
    const int tid  = threadIdx.x;
    const int warp = tid >> 5, lane = tid & 31;
    const int wm = warp >> 2, wn = warp & 3;

#pragma unroll
    for (int i = 0; i < 4; i++)
#pragma unroll
        for (int j = 0; j < 4; j++)
#pragma unroll
            for (int r = 0; r < 4; r++) G.a[i][j][r] = 0.f;

    const uint32_t aoff = (wm * 64 + (lane & 7) + ((lane >> 3) & 1) * 8) * 80
                        + (lane >> 4) * 16;
    const uint32_t boff = GPL1 + (wn * 32 + (lane & 7) + ((lane >> 3) & 1) * 8) * 80
                        + (lane >> 4) * 16;

    auto fill = [&](int c) {
        int st = c & 3, k0 = c * 32;
        uint32_t sb = smu + (uint32_t)st * GST1;
#pragma unroll
        for (int u = 0; u < 4; u++) {
            int f = tid + u * 256;               // 1024 cp16: 512/plane
            int pl = f >> 9, idx = f & 511;
            int row = idx >> 2, g4 = idx & 3;
            const __half* sp = (pl == 0) ? (A + (size_t)m0 * E_DIM)
                                         : (B + (size_t)n0 * E_DIM);
            cp16(sb + (uint32_t)pl * GPL1 + row * 80 + g4 * 16,
                 sp + (size_t)row * E_DIM + k0 + g4 * 8);
        }
    };
    fill(0);
    asm volatile("cp.async.commit_group;" ::: "memory");
    fill(1);
    asm volatile("cp.async.commit_group;" ::: "memory");
    fill(2);
    asm volatile("cp.async.commit_group;" ::: "memory");

    for (int c = 0; c < 32; c++) {
        asm volatile("cp.async.wait_group 2;" ::: "memory");
        __syncthreads();

        const uint32_t sb = smu + (uint32_t)(c & 3) * GST1;
#pragma unroll
        for (int kk = 0; kk < 2; kk++) {
            uint32_t a[4][4], b[2][4];
#pragma unroll
            for (int i = 0; i < 4; i++)
                ldsm4(a[i][0], a[i][1], a[i][2], a[i][3],
                      sb + aoff + (uint32_t)(i * 16 * 80 + kk * 32));
#pragma unroll
            for (int p = 0; p < 2; p++)
                ldsm4(b[p][0], b[p][1], b[p][2], b[p][3],
                      sb + boff + (uint32_t)(p * 16 * 80 + kk * 32));
#pragma unroll
            for (int i = 0; i < 4; i++)
#pragma unroll
                for (int p = 0; p < 2; p++) {
                    mma_f16(G.a[i][2*p],   a[i][0], a[i][1], a[i][2], a[i][3],
                            b[p][0], b[p][2]);
                    mma_f16(G.a[i][2*p+1], a[i][0], a[i][1], a[i][2], a[i][3],
                            b[p][1], b[p][3]);
                }
        }
        if (c + 3 < 32) fill(c + 3);
        asm volatile("cp.async.commit_group;" ::: "memory");
    }
}

// Q/K projections (2-pass): gridDim.z selects Q or K.
__global__ __launch_bounds__(256, 2)
void gemm_qk_kernel(const float* __restrict__ bq, const float* __restrict__ bk)
{
    extern __shared__ char smc[];
    const int z = blockIdx.z;
    const int m0 = blockIdx.y * 128, n0 = blockIdx.x * 128;
    GemmAcc G;
    gemm2_core(g_x16, g_wh + ((size_t)z << 20), g_wl + ((size_t)z << 20),
               m0, n0, smc, G);

    const float* bias = (z == 0) ? bq : bk;
    const int warp = threadIdx.x >> 5, lane = threadIdx.x & 31;
    const int wm = warp >> 2, wn = warp & 3;
#pragma unroll
    for (int i = 0; i < 4; i++) {
#pragma unroll
        for (int j = 0; j < 4; j++) {
            int row = m0 + wm * 64 + i * 16 + (lane >> 2);
            int col = n0 + wn * 32 + j * 8 + (lane & 3) * 2;
#pragma unroll
            for (int rp = 0; rp < 2; rp++) {
                int rr = row + rp * 8;
                float v0 = G.a[i][j][rp * 2 + 0] + bias[col];
                float v1 = G.a[i][j][rp * 2 + 1] + bias[col + 1];
                int hh = col >> 6, dd = col & 63;
                size_t off = ((size_t)hh * S_LEN + rr) * HD + dd;
                uint32_t hp, lp;
                if (z == 0) {
                    split2h(v0 * LOG2E, v1 * LOG2E, hp, lp);
                    *(uint32_t*)(g_qh + off) = hp;
                    *(uint32_t*)(g_ql + off) = lp;
                } else {
                    split2h(v0, v1, hp, lp);
                    *(uint32_t*)(g_kh + off) = hp;
                    *(uint32_t*)(g_kl + off) = lp;
                }
            }
        }
    }
}

// V projection (1-pass fp16).
__global__ __launch_bounds__(256, 2)
void gemm_v_kernel(const float* __restrict__ bv)
{
    extern __shared__ char smc[];
    const int m0 = blockIdx.y * 128, n0 = blockIdx.x * 128;
    GemmAcc G;
    gemm1_core(g_x16, g_wh + (2ull << 20), m0, n0, smc, G);

    const int warp = threadIdx.x >> 5, lane = threadIdx.x & 31;
    const int wm = warp >> 2, wn = warp & 3;
#pragma unroll
    for (int i = 0; i < 4; i++) {
#pragma unroll
        for (int j = 0; j < 4; j++) {
            int row = m0 + wm * 64 + i * 16 + (lane >> 2);
            int col = n0 + wn * 32 + j * 8 + (lane & 3) * 2;
#pragma unroll
            for (int rp = 0; rp < 2; rp++) {
                int rr = row + rp * 8;
                float v0 = G.a[i][j][rp * 2 + 0] + bv[col];
                float v1 = G.a[i][j][rp * 2 + 1] + bv[col + 1];
                int hh = col >> 6, dd = col & 63;
                *(uint32_t*)(g_vh + ((size_t)hh * S_LEN + rr) * HD + dd) = pack_h2(v0, v1);
            }
        }
    }
}

// Output GEMM (1-pass fp16): out = att @ wo^T + bo (fp32 [s][e]).
__global__ __launch_bounds__(256, 2)
void gemm_out_kernel(const float* __restrict__ bo, float* __restrict__ dst)
{
    extern __shared__ char smc[];
    const int m0 = blockIdx.y * 128, n0 = blockIdx.x * 128;
    GemmAcc G;
    gemm1_core(g_a16, g_wh + (3ull << 20), m0, n0, smc, G);

    const int warp = threadIdx.x >> 5, lane = threadIdx.x & 31;
    const int wm = warp >> 2, wn = warp & 3;
#pragma unroll
    for (int i = 0; i < 4; i++) {
#pragma unroll
        for (int j = 0; j < 4; j++) {
            int row = m0 + wm * 64 + i * 16 + (lane >> 2);
            int col = n0 + wn * 32 + j * 8 + (lane & 3) * 2;
#pragma unroll
            for (int rp = 0; rp < 2; rp++) {
                int rr = row + rp * 8;
                float v0 = G.a[i][j][rp * 2 + 0] + bo[col];
                float v1 = G.a[i][j][rp * 2 + 1] + bo[col + 1];
                *(float2*)(dst + (size_t)rr * E_DIM + col) = make_float2(v0, v1);
            }
        }
    }
}

// ---------------------------------------------------------------------------
// Windowed attention (unchanged from R14): QK fp16 3-pass, PV fp16 1-pass,
// log2-domain softmax, cp.async double-buffered K/V, closed-form pad tiles,
// per-warp relevance/mask skip. smem: Qh Ql | 2 x (Kh Kl V) = 8 x 18432B.
// ---------------------------------------------------------------------------
#define RS   72
#define REG  (128 * RS * 2)
__global__ __launch_bounds__(256)
void attn_kernel()
{
    extern __shared__ char smc[];
    const uint32_t smu = (uint32_t)__cvta_generic_to_shared(smc);
    const uint32_t QHI = smu, QLO = smu + REG;

    const int tid  = threadIdx.x;
    const int warp = tid >> 5, lane = tid & 31;
    const int q0   = blockIdx.x * 128;
    const int w    = blockIdx.y;
    const int h    = blockIdx.z;
    const int base = w * WSZ - WSZ;
    const int Q0w  = q0 + warp * 16;

    const uint32_t a_lane = (uint32_t)(((warp * 16 + (lane & 7) + ((lane >> 3) & 1) * 8) * RS
                                        + (lane >> 4) * 8) * 2);
    const uint32_t kb_lane = (uint32_t)((((lane & 7) + ((lane >> 3) & 1) * 8) * RS
                                        + (lane >> 4) * 8) * 2);
    const uint32_t vb_lane = (uint32_t)((((lane & 7) + ((lane >> 4) & 1) * 8) * RS
                                        + ((lane >> 3) & 1) * 8) * 2);

    int tiles[12], nt = 0, npad = 0;
#pragma unroll
    for (int kt = 0; kt < NTILE; kt++) {
        int c0 = kt * 128, t0 = base + c0;
        if (t0 < 0 || t0 >= S_LEN) { npad++; continue; }
        if ((c0 + 127 >= q0) && (c0 <= q0 + 127 + 1024)) tiles[nt++] = kt;
    }

    {
        size_t qoff = ((size_t)h * S_LEN + w * WSZ + q0) * HD;
        for (int f = tid; f < 1024; f += 256) {
            int r = f >> 3, c = f & 7;
            uint32_t so = r * 144 + c * 16;
            size_t go = qoff + (size_t)r * HD + c * 8;
            cp16(QHI + so, g_qh + go);
            cp16(QLO + so, g_ql + go);
        }
    }
    const size_t hoff = (size_t)h * S_LEN * HD;
    auto fetch = [&](int kt, int b) {
        int t0 = base + kt * 128;
        uint32_t sb = smu + (uint32_t)(2 + 3 * b) * REG;
        size_t gb = hoff + (size_t)t0 * HD;
        for (int f = tid; f < 1024; f += 256) {
            int r = f >> 3, c = f & 7;
            uint32_t so = sb + r * 144 + c * 16;
            size_t go = gb + (size_t)r * HD + c * 8;
            cp16(so,           g_kh + go);
            cp16(so + REG,     g_kl + go);
            cp16(so + 2 * REG, g_vh + go);
        }
    };
    fetch(tiles[0], 0);
    asm volatile("cp.async.commit_group;" ::: "memory");
    if (nt > 1) {
        fetch(tiles[1], 1);
        asm volatile("cp.async.commit_group;" ::: "memory");
    }

    float m0r = -1e30f, m1r = -1e30f, l0r = 0.f, l1r = 0.f;
    float o[8][4];
#pragma unroll
    for (int f = 0; f < 8; f++)
#pragma unroll
        for (int e = 0; e < 4; e++) o[f][e] = 0.f;

    const int r0 = Q0w + (lane >> 2);
    const int r1 = r0 + 8;

    for (int i = 0; i < nt; i++) {
        if (i + 1 < nt) asm volatile("cp.async.wait_group 1;" ::: "memory");
        else            asm volatile("cp.async.wait_group 0;" ::: "memory");
        __syncthreads();

        if (i == 0) {
            const __half* qh = (const __half*)smc;
            const __half* ql = (const __half*)(smc + REG);
            int lr0 = warp * 16 + (lane >> 2);
            float qs0 = 0.f, qs1 = 0.f;
#pragma unroll
            for (int d = 0; d < HD; d++) {
                qs0 += __half2float(qh[lr0 * RS + d]) + __half2float(ql[lr0 * RS + d]);
                qs1 += __half2float(qh[(lr0 + 8) * RS + d]) + __half2float(ql[(lr0 + 8) * RS + d]);
            }
            if (npad) {
                float s0 = -qs0, s1 = -qs1;
                float nm0 = fmaxf(m0r, s0), nm1 = fmaxf(m1r, s1);
                float cr0 = ex2(m0r - nm0), cr1 = ex2(m1r - nm1);
                m0r = nm0; m1r = nm1;
                float p0 = ex2(s0 - nm0) * (128.f * npad);
                float p1 = ex2(s1 - nm1) * (128.f * npad);
                l0r = l0r * cr0 + p0;
                l1r = l1r * cr1 + p1;
#pragma unroll
                for (int f = 0; f < 8; f++) {
                    o[f][0] = o[f][0] * cr0 - p0;
                    o[f][1] = o[f][1] * cr0 - p0;
                    o[f][2] = o[f][2] * cr1 - p1;
                    o[f][3] = o[f][3] * cr1 - p1;
                }
            }
        }

        const int kt = tiles[i];
        const int c0 = kt * 128;
        const bool relevant = (c0 + 127 >= Q0w) && (c0 <= Q0w + 1039);

        if (relevant) {
            const uint32_t BB  = smu + (uint32_t)(2 + 3 * (i & 1)) * REG;
            const uint32_t KHI = BB, KLO = BB + REG, VHI = BB + 2 * REG;

            float sS[16][4];
#pragma unroll
            for (int f = 0; f < 16; f++)
#pragma unroll
                for (int e = 0; e < 4; e++) sS[f][e] = 0.f;

#pragma unroll
            for (int s = 0; s < 4; s++) {
                uint32_t ah0, ah1, ah2, ah3, al0, al1, al2, al3;
                ldsm4(ah0, ah1, ah2, ah3, QHI + a_lane + s * 32);
                ldsm4(al0, al1, al2, al3, QLO + a_lane + s * 32);
#pragma unroll
                for (int p = 0; p < 8; p++) {
                    uint32_t bh0, bh1, bh2, bh3, bl0, bl1, bl2, bl3;
                    ldsm4(bh0, bh1, bh2, bh3, KHI + kb_lane + p * 2304 + s * 32);
                    ldsm4(bl0, bl1, bl2, bl3, KLO + kb_lane + p * 2304 + s * 32);
                    mma_f16(sS[2*p],   ah0, ah1, ah2, ah3, bh0, bh2);
                    mma_f16(sS[2*p+1], ah0, ah1, ah2, ah3, bh1, bh3);
                    mma_f16(sS[2*p],   ah0, ah1, ah2, ah3, bl0, bl2);
                    mma_f16(sS[2*p+1], ah0, ah1, ah2, ah3, bl1, bl3);
                    mma_f16(sS[2*p],   al0, al1, al2, al3, bh0, bh2);
                    mma_f16(sS[2*p+1], al0, al1, al2, al3, bh1, bh3);
                }
            }

            const bool needmask = !((c0 >= Q0w + 15) && (c0 + 127 <= Q0w + 1024));
            if (needmask) {
#pragma unroll
                for (int f = 0; f < 16; f++) {
                    int c = c0 + f * 8 + (lane & 3) * 2;
#pragma unroll
                    for (int e = 0; e < 2; e++) {
                        int cc = c + e;
                        if (!(cc >= r0 && cc <= r0 + 1024)) sS[f][e]     = -1e30f;
                        if (!(cc >= r1 && cc <= r1 + 1024)) sS[f][2 + e] = -1e30f;
                    }
                }
            }

            float tm0 = -1e30f, tm1 = -1e30f;
#pragma unroll
            for (int f = 0; f < 16; f++) {
                tm0 = fmaxf(tm0, fmaxf(sS[f][0], sS[f][1]));
                tm1 = fmaxf(tm1, fmaxf(sS[f][2], sS[f][3]));
            }
            tm0 = fmaxf(tm0, __shfl_xor_sync(0xffffffffu, tm0, 1));
            tm0 = fmaxf(tm0, __shfl_xor_sync(0xffffffffu, tm0, 2));
            tm1 = fmaxf(tm1, __shfl_xor_sync(0xffffffffu, tm1, 1));
            tm1 = fmaxf(tm1, __shfl_xor_sync(0xffffffffu, tm1, 2));
            float nm0 = fmaxf(m0r, tm0), nm1 = fmaxf(m1r, tm1);
            float cr0 = ex2(m0r - nm0), cr1 = ex2(m1r - nm1);
            m0r = nm0; m1r = nm1;
#pragma unroll
            for (int f = 0; f < 8; f++) {
                o[f][0] *= cr0; o[f][1] *= cr0;
                o[f][2] *= cr1; o[f][3] *= cr1;
            }
            float la0 = 0.f, la1 = 0.f;

#pragma unroll
            for (int s2 = 0; s2 < 8; s2++) {
                int f0 = 2 * s2, f1 = f0 + 1;
                float p00 = ex2(sS[f0][0] - m0r), p01 = ex2(sS[f0][1] - m0r);
                float p02 = ex2(sS[f0][2] - m1r), p03 = ex2(sS[f0][3] - m1r);
                float p10 = ex2(sS[f1][0] - m0r), p11 = ex2(sS[f1][1] - m0r);
                float p12 = ex2(sS[f1][2] - m1r), p13 = ex2(sS[f1][3] - m1r);
                la0 += p00 + p01 + p10 + p11;
                la1 += p02 + p03 + p12 + p13;
                uint32_t ah0 = pack_h2(p00, p01);
                uint32_t ah1 = pack_h2(p02, p03);
                uint32_t ah2 = pack_h2(p10, p11);
                uint32_t ah3 = pack_h2(p12, p13);
#pragma unroll
                for (int q = 0; q < 4; q++) {
                    uint32_t bh0, bh1, bh2, bh3;
                    ldsm4t(bh0, bh1, bh2, bh3, VHI + vb_lane + s2 * 2304 + q * 32);
                    mma_f16(o[2*q],   ah0, ah1, ah2, ah3, bh0, bh2);
                    mma_f16(o[2*q+1], ah0, ah1, ah2, ah3, bh1, bh3);
                }
            }
            la0 += __shfl_xor_sync(0xffffffffu, la0, 1);
            la0 += __shfl_xor_sync(0xffffffffu, la0, 2);
            la1 += __shfl_xor_sync(0xffffffffu, la1, 1);
            la1 += __shfl_xor_sync(0xffffffffu, la1, 2);
            l0r = l0r * cr0 + la0;
            l1r = l1r * cr1 + la1;
        }

        __syncthreads();
        if (i + 2 < nt) {
            fetch(tiles[i + 2], i & 1);
            asm volatile("cp.async.commit_group;" ::: "memory");
        }
    }

    const float i0 = 1.f / l0r, i1 = 1.f / l1r;
    const int sg0 = w * WSZ + q0 + warp * 16 + (lane >> 2);
    const int e0  = h * HD + (lane & 3) * 2;
    size_t o0 = (size_t)sg0 * E_DIM + e0;
    size_t o1 = o0 + 8 * E_DIM;
#pragma unroll
    for (int f = 0; f < 8; f++) {
        *(uint32_t*)(g_a16 + o0 + f * 8) = pack_h2(o[f][0] * i0, o[f][1] * i0);
        *(uint32_t*)(g_a16 + o1 + f * 8) = pack_h2(o[f][2] * i1, o[f][3] * i1);
    }
}

// ---------------------------------------------------------------------------
extern "C" void kernel_launch(void* const* d_in, const int* in_sizes, int n_in,
                              void* d_out, int out_size)
{
    const float* x  = (const float*)d_in[0];
    const float* wq = (const float*)d_in[1];
    const float* bq = (const float*)d_in[2];
    const float* wk = (const float*)d_in[3];
    const float* bk = (const float*)d_in[4];
    const float* wv = (const float*)d_in[5];
    const float* bv = (const float*)d_in[6];
    const float* wo = (const float*)d_in[7];
    const float* bo = (const float*)d_in[8];
    float* out = (float*)d_out;

    const int gsm2 = 4 * GST2;          // 73728
    const int gsm1 = 4 * GST1;          // 81920
    cudaFuncSetAttribute(gemm_qk_kernel, cudaFuncAttributeMaxDynamicSharedMemorySize, gsm2);
    cudaFuncSetAttribute(gemm_v_kernel,  cudaFuncAttributeMaxDynamicSharedMemorySize, gsm1);
    cudaFuncSetAttribute(gemm_out_kernel, cudaFuncAttributeMaxDynamicSharedMemorySize, gsm1);
    const int asm_b = 8 * REG;          // 147456
    cudaFuncSetAttribute(attn_kernel, cudaFuncAttributeMaxDynamicSharedMemorySize, asm_b);

    presplit_kernel<<<8192, 256>>>((const float4*)x, (const float4*)wq, (const float4*)wk,
                                   (const float4*)wv, (const float4*)wo);

    dim3 gqk(E_DIM / 128, S_LEN / 128, 2);
    gemm_qk_kernel<<<gqk, 256, gsm2>>>(bq, bk);
    dim3 gg(E_DIM / 128, S_LEN / 128);
    gemm_v_kernel<<<gg, 256, gsm1>>>(bv);

    dim3 ga(4, 8, 16);
    attn_kernel<<<ga, 256, asm_b>>>();

    gemm_out_kernel<<<gg, 256, gsm1>>>(bo, out);
}

// round 17
// speedup vs baseline: 1.3337x; 1.1239x over previous
#include <cuda_runtime.h>
#include <cuda_bf16.h>
#include <cuda_fp16.h>
#include <cstdint>

#define S_LEN 4096
#define E_DIM 1024
#define H_NUM 16
#define HD    64
#define WSZ   512
#define NTILE 12
#define LOG2E 1.4426950408889634f

// Scratch (allocation-free rule: __device__ globals). fp16 planes.
#define PLANE (H_NUM * S_LEN * HD)
__device__ __half g_q16[PLANE];                    // Q * log2(e), fp16 single
__device__ __half g_kh[PLANE], g_kl[PLANE];        // K fp16 split
__device__ __half g_vh[PLANE];                     // V fp16 single plane
__device__ __half g_x16[4 << 20];                  // x fp16, [s][e]
__device__ __half g_wh[4 << 20], g_wl[4 << 20];    // wq|wk|wv|wo fp16 split, [n][k]
__device__ __half g_a16[4 << 20];                  // attention out fp16, [s][e]

// ---------------------------------------------------------------------------
// helpers
// ---------------------------------------------------------------------------
__device__ __forceinline__ float ex2(float x) {
    float r;
    asm("ex2.approx.f32 %0, %1;" : "=f"(r) : "f"(x));
    return r;
}
__device__ __forceinline__ void ldsm4(uint32_t& r0, uint32_t& r1, uint32_t& r2,
                                      uint32_t& r3, uint32_t addr) {
    asm volatile("ldmatrix.sync.aligned.m8n8.x4.shared.b16 {%0,%1,%2,%3}, [%4];"
                 : "=r"(r0), "=r"(r1), "=r"(r2), "=r"(r3) : "r"(addr));
}
__device__ __forceinline__ void ldsm4t(uint32_t& r0, uint32_t& r1, uint32_t& r2,
                                       uint32_t& r3, uint32_t addr) {
    asm volatile("ldmatrix.sync.aligned.m8n8.x4.trans.shared.b16 {%0,%1,%2,%3}, [%4];"
                 : "=r"(r0), "=r"(r1), "=r"(r2), "=r"(r3) : "r"(addr));
}
__device__ __forceinline__ void mma_f16(float c[4],
                                        uint32_t a0, uint32_t a1, uint32_t a2, uint32_t a3,
                                        uint32_t b0, uint32_t b1) {
    asm volatile(
        "mma.sync.aligned.m16n8k16.row.col.f32.f16.f16.f32 "
        "{%0,%1,%2,%3},{%4,%5,%6,%7},{%8,%9},{%0,%1,%2,%3};"
        : "+f"(c[0]), "+f"(c[1]), "+f"(c[2]), "+f"(c[3])
        : "r"(a0), "r"(a1), "r"(a2), "r"(a3), "r"(b0), "r"(b1));
}
__device__ __forceinline__ uint32_t pack_h2(float x0, float x1) {
    uint32_t r;
    asm("cvt.rn.f16x2.f32 %0, %1, %2;" : "=r"(r) : "f"(x1), "f"(x0));
    return r;
}
__device__ __forceinline__ void split2h(float x0, float x1, uint32_t& h, uint32_t& l) {
    h = pack_h2(x0, x1);
    __half2 hv = *reinterpret_cast<__half2*>(&h);
    l = pack_h2(x0 - __half2float(hv.x), x1 - __half2float(hv.y));
}
__device__ __forceinline__ void cp16(uint32_t s, const void* g) {
    asm volatile("cp.async.cg.shared.global [%0], [%1], 16;" :: "r"(s), "l"(g));
}

// ---------------------------------------------------------------------------
// Presplit: x -> fp16 single plane; wq|wk|wv|wo -> fp16 hi/lo planes.
// ---------------------------------------------------------------------------
__global__ __launch_bounds__(256)
void presplit_kernel(const float4* __restrict__ x,  const float4* __restrict__ wq,
                     const float4* __restrict__ wk, const float4* __restrict__ wv,
                     const float4* __restrict__ wo)
{
    int i = blockIdx.x * 256 + threadIdx.x;          // 2M float4
    if (i < (1 << 20)) {
        float4 v = x[i];
        ((uint2*)g_x16)[i] = make_uint2(pack_h2(v.x, v.y), pack_h2(v.z, v.w));
    } else {
        int t = i - (1 << 20);
        int ws = t >> 18;
        int j = t & ((1 << 18) - 1);
        const float4* src = (ws == 0) ? wq : (ws == 1) ? wk : (ws == 2) ? wv : wo;
        float4 v = src[j];
        uint32_t h01, l01, h23, l23;
        split2h(v.x, v.y, h01, l01);
        split2h(v.z, v.w, h23, l23);
        size_t o = ((size_t)ws << 18) + j;
        ((uint2*)g_wh)[o] = make_uint2(h01, h23);
        ((uint2*)g_wl)[o] = make_uint2(l01, l23);
    }
}

struct GemmAcc { float a[4][4][4]; };

// ---------------------------------------------------------------------------
// 2-pass fp16 GEMM core (Q/K projections): D = A·Bh^T + A·Bl^T, K=1024.
// BK=16, 4-stage ring, fill(c+3) AFTER compute, 64 iters. 48B row stride.
// ---------------------------------------------------------------------------
#define GPL2 6144
#define GST2 (3 * GPL2)

__device__ __forceinline__ void gemm2_core(const __half* __restrict__ A,
                                           const __half* __restrict__ Bh,
                                           const __half* __restrict__ Bl,
                                           int m0, int n0, char* smc, GemmAcc& G)
{
    const uint32_t smu = (uint32_t)__cvta_generic_to_shared(smc);
    const int tid  = threadIdx.x;
    const int warp = tid >> 5, lane = tid & 31;
    const int wm = warp >> 2, wn = warp & 3;

#pragma unroll
    for (int i = 0; i < 4; i++)
#pragma unroll
        for (int j = 0; j < 4; j++)
#pragma unroll
            for (int r = 0; r < 4; r++) G.a[i][j][r] = 0.f;

    const uint32_t aoff = (wm * 64 + (lane & 7) + ((lane >> 3) & 1) * 8) * 48
                        + (lane >> 4) * 16;
    const uint32_t boff = GPL2 + (wn * 32 + (lane & 7) + ((lane >> 3) & 1) * 8) * 48
                        + (lane >> 4) * 16;

    auto fill = [&](int c) {
        int st = c & 3, k0 = c * 16;
        uint32_t sb = smu + (uint32_t)st * GST2;
#pragma unroll
        for (int u = 0; u < 3; u++) {
            int f = tid + u * 256;
            int pl = f >> 8, idx = f & 255;
            int row = idx >> 1, g8 = idx & 1;
            const __half* sp = (pl == 0) ? (A + (size_t)m0 * E_DIM)
                             : (pl == 1) ? (Bh + (size_t)n0 * E_DIM)
                                         : (Bl + (size_t)n0 * E_DIM);
            cp16(sb + (uint32_t)pl * GPL2 + row * 48 + g8 * 16,
                 sp + (size_t)row * E_DIM + k0 + g8 * 8);
        }
    };
    fill(0);
    asm volatile("cp.async.commit_group;" ::: "memory");
    fill(1);
    asm volatile("cp.async.commit_group;" ::: "memory");
    fill(2);
    asm volatile("cp.async.commit_group;" ::: "memory");

    for (int c = 0; c < 64; c++) {
        asm volatile("cp.async.wait_group 2;" ::: "memory");
        __syncthreads();

        const uint32_t sb = smu + (uint32_t)(c & 3) * GST2;
        uint32_t a[4][4], bh[2][4], bl[2][4];
#pragma unroll
        for (int i = 0; i < 4; i++)
            ldsm4(a[i][0], a[i][1], a[i][2], a[i][3],
                  sb + aoff + (uint32_t)(i * 16 * 48));
#pragma unroll
        for (int p = 0; p < 2; p++) {
            ldsm4(bh[p][0], bh[p][1], bh[p][2], bh[p][3],
                  sb + boff + (uint32_t)(p * 16 * 48));
            ldsm4(bl[p][0], bl[p][1], bl[p][2], bl[p][3],
                  sb + GPL2 + boff + (uint32_t)(p * 16 * 48));
        }
#pragma unroll
        for (int i = 0; i < 4; i++)
#pragma unroll
            for (int p = 0; p < 2; p++) {
                mma_f16(G.a[i][2*p],   a[i][0], a[i][1], a[i][2], a[i][3],
                        bh[p][0], bh[p][2]);
                mma_f16(G.a[i][2*p+1], a[i][0], a[i][1], a[i][2], a[i][3],
                        bh[p][1], bh[p][3]);
                mma_f16(G.a[i][2*p],   a[i][0], a[i][1], a[i][2], a[i][3],
                        bl[p][0], bl[p][2]);
                mma_f16(G.a[i][2*p+1], a[i][0], a[i][1], a[i][2], a[i][3],
                        bl[p][1], bl[p][3]);
            }
        if (c + 3 < 64) fill(c + 3);
        asm volatile("cp.async.commit_group;" ::: "memory");
    }
}

// ---------------------------------------------------------------------------
// 1-pass fp16 GEMM core (V projection + output GEMM): D = A·B^T, K=1024.
// BK=32, 4-stage ring, fill(c+3) AFTER compute, 32 iters. 80B row stride.
// ---------------------------------------------------------------------------
#define GPL1 10240
#define GST1 (2 * GPL1)

__device__ __forceinline__ void gemm1_core(const __half* __restrict__ A,
                                           const __half* __restrict__ B,
                                           int m0, int n0, char* smc, GemmAcc& G)
{
    const uint32_t smu = (uint32_t)__cvta_generic_to_shared(smc);
    const int tid  = threadIdx.x;
    const int warp = tid >> 5, lane = tid & 31;
    const int wm = warp >> 2, wn = warp & 3;

#pragma unroll
    for (int i = 0; i < 4; i++)
#pragma unroll
        for (int j = 0; j < 4; j++)
#pragma unroll
            for (int r = 0; r < 4; r++) G.a[i][j][r] = 0.f;

    const uint32_t aoff = (wm * 64 + (lane & 7) + ((lane >> 3) & 1) * 8) * 80
                        + (lane >> 4) * 16;
    const uint32_t boff = GPL1 + (wn * 32 + (lane & 7) + ((lane >> 3) & 1) * 8) * 80
                        + (lane >> 4) * 16;

    auto fill = [&](int c) {
        int st = c & 3, k0 = c * 32;
        uint32_t sb = smu + (uint32_t)st * GST1;
#pragma unroll
        for (int u = 0; u < 4; u++) {
            int f = tid + u * 256;
            int pl = f >> 9, idx = f & 511;
            int row = idx >> 2, g4 = idx & 3;
            const __half* sp = (pl == 0) ? (A + (size_t)m0 * E_DIM)
                                         : (B + (size_t)n0 * E_DIM);
            cp16(sb + (uint32_t)pl * GPL1 + row * 80 + g4 * 16,
                 sp + (size_t)row * E_DIM + k0 + g4 * 8);
        }
    };
    fill(0);
    asm volatile("cp.async.commit_group;" ::: "memory");
    fill(1);
    asm volatile("cp.async.commit_group;" ::: "memory");
    fill(2);
    asm volatile("cp.async.commit_group;" ::: "memory");

    for (int c = 0; c < 32; c++) {
        asm volatile("cp.async.wait_group 2;" ::: "memory");
        __syncthreads();

        const uint32_t sb = smu + (uint32_t)(c & 3) * GST1;
#pragma unroll
        for (int kk = 0; kk < 2; kk++) {
            uint32_t a[4][4], b[2][4];
#pragma unroll
            for (int i = 0; i < 4; i++)
                ldsm4(a[i][0], a[i][1], a[i][2], a[i][3],
                      sb + aoff + (uint32_t)(i * 16 * 80 + kk * 32));
#pragma unroll
            for (int p = 0; p < 2; p++)
                ldsm4(b[p][0], b[p][1], b[p][2], b[p][3],
                      sb + boff + (uint32_t)(p * 16 * 80 + kk * 32));
#pragma unroll
            for (int i = 0; i < 4; i++)
#pragma unroll
                for (int p = 0; p < 2; p++) {
                    mma_f16(G.a[i][2*p],   a[i][0], a[i][1], a[i][2], a[i][3],
                            b[p][0], b[p][2]);
                    mma_f16(G.a[i][2*p+1], a[i][0], a[i][1], a[i][2], a[i][3],
                            b[p][1], b[p][3]);
                }
        }
        if (c + 3 < 32) fill(c + 3);
        asm volatile("cp.async.commit_group;" ::: "memory");
    }
}

// Q/K projections (2-pass): gridDim.z selects Q or K.
__global__ __launch_bounds__(256, 2)
void gemm_qk_kernel(const float* __restrict__ bq, const float* __restrict__ bk)
{
    extern __shared__ char smc[];
    const int z = blockIdx.z;
    const int m0 = blockIdx.y * 128, n0 = blockIdx.x * 128;
    GemmAcc G;
    gemm2_core(g_x16, g_wh + ((size_t)z << 20), g_wl + ((size_t)z << 20),
               m0, n0, smc, G);

    const float* bias = (z == 0) ? bq : bk;
    const int warp = threadIdx.x >> 5, lane = threadIdx.x & 31;
    const int wm = warp >> 2, wn = warp & 3;
#pragma unroll
    for (int i = 0; i < 4; i++) {
#pragma unroll
        for (int j = 0; j < 4; j++) {
            int row = m0 + wm * 64 + i * 16 + (lane >> 2);
            int col = n0 + wn * 32 + j * 8 + (lane & 3) * 2;
#pragma unroll
            for (int rp = 0; rp < 2; rp++) {
                int rr = row + rp * 8;
                float v0 = G.a[i][j][rp * 2 + 0] + bias[col];
                float v1 = G.a[i][j][rp * 2 + 1] + bias[col + 1];
                int hh = col >> 6, dd = col & 63;
                size_t off = ((size_t)hh * S_LEN + rr) * HD + dd;
                if (z == 0) {
                    *(uint32_t*)(g_q16 + off) = pack_h2(v0 * LOG2E, v1 * LOG2E);
                } else {
                    uint32_t hp, lp;
                    split2h(v0, v1, hp, lp);
                    *(uint32_t*)(g_kh + off) = hp;
                    *(uint32_t*)(g_kl + off) = lp;
                }
            }
        }
    }
}

// V projection (1-pass fp16).
__global__ __launch_bounds__(256, 2)
void gemm_v_kernel(const float* __restrict__ bv)
{
    extern __shared__ char smc[];
    const int m0 = blockIdx.y * 128, n0 = blockIdx.x * 128;
    GemmAcc G;
    gemm1_core(g_x16, g_wh + (2ull << 20), m0, n0, smc, G);

    const int warp = threadIdx.x >> 5, lane = threadIdx.x & 31;
    const int wm = warp >> 2, wn = warp & 3;
#pragma unroll
    for (int i = 0; i < 4; i++) {
#pragma unroll
        for (int j = 0; j < 4; j++) {
            int row = m0 + wm * 64 + i * 16 + (lane >> 2);
            int col = n0 + wn * 32 + j * 8 + (lane & 3) * 2;
#pragma unroll
            for (int rp = 0; rp < 2; rp++) {
                int rr = row + rp * 8;
                float v0 = G.a[i][j][rp * 2 + 0] + bv[col];
                float v1 = G.a[i][j][rp * 2 + 1] + bv[col + 1];
                int hh = col >> 6, dd = col & 63;
                *(uint32_t*)(g_vh + ((size_t)hh * S_LEN + rr) * HD + dd) = pack_h2(v0, v1);
            }
        }
    }
}

// Output GEMM (1-pass fp16): out = att @ wo^T + bo (fp32 [s][e]).
__global__ __launch_bounds__(256, 2)
void gemm_out_kernel(const float* __restrict__ bo, float* __restrict__ dst)
{
    extern __shared__ char smc[];
    const int m0 = blockIdx.y * 128, n0 = blockIdx.x * 128;
    GemmAcc G;
    gemm1_core(g_a16, g_wh + (3ull << 20), m0, n0, smc, G);

    const int warp = threadIdx.x >> 5, lane = threadIdx.x & 31;
    const int wm = warp >> 2, wn = warp & 3;
#pragma unroll
    for (int i = 0; i < 4; i++) {
#pragma unroll
        for (int j = 0; j < 4; j++) {
            int row = m0 + wm * 64 + i * 16 + (lane >> 2);
            int col = n0 + wn * 32 + j * 8 + (lane & 3) * 2;
#pragma unroll
            for (int rp = 0; rp < 2; rp++) {
                int rr = row + rp * 8;
                float v0 = G.a[i][j][rp * 2 + 0] + bo[col];
                float v1 = G.a[i][j][rp * 2 + 1] + bo[col + 1];
                *(float2*)(dst + (size_t)rr * E_DIM + col) = make_float2(v0, v1);
            }
        }
    }
}

// ---------------------------------------------------------------------------
// Windowed attention: Q single fp16 plane (QK 2-pass: Q·Kh + Q·Kl), PV fp16
// 1-pass, log2-domain softmax, closed-form pad tiles, per-warp skip.
// SINGLE-buffered smem (Q | Kh | Kl | V = 4 x 18432B = 73.7KB) -> 2 CTAs/SM;
// cross-CTA overlap hides cp.async latency. __launch_bounds__(256,2).
// ---------------------------------------------------------------------------
#define RS   72
#define REG  (128 * RS * 2)
__global__ __launch_bounds__(256, 2)
void attn_kernel()
{
    extern __shared__ char smc[];
    const uint32_t smu = (uint32_t)__cvta_generic_to_shared(smc);
    const uint32_t QHI = smu, KHI = smu + REG, KLO = smu + 2 * REG, VHI = smu + 3 * REG;

    const int tid  = threadIdx.x;
    const int warp = tid >> 5, lane = tid & 31;
    const int q0   = blockIdx.x * 128;
    const int w    = blockIdx.y;
    const int h    = blockIdx.z;
    const int base = w * WSZ - WSZ;
    const int Q0w  = q0 + warp * 16;

    const uint32_t a_lane = (uint32_t)(((warp * 16 + (lane & 7) + ((lane >> 3) & 1) * 8) * RS
                                        + (lane >> 4) * 8) * 2);
    const uint32_t kb_lane = (uint32_t)((((lane & 7) + ((lane >> 3) & 1) * 8) * RS
                                        + (lane >> 4) * 8) * 2);
    const uint32_t vb_lane = (uint32_t)((((lane & 7) + ((lane >> 4) & 1) * 8) * RS
                                        + ((lane >> 3) & 1) * 8) * 2);

    int tiles[12], nt = 0, npad = 0;
#pragma unroll
    for (int kt = 0; kt < NTILE; kt++) {
        int c0 = kt * 128, t0 = base + c0;
        if (t0 < 0 || t0 >= S_LEN) { npad++; continue; }
        if ((c0 + 127 >= q0) && (c0 <= q0 + 127 + 1024)) tiles[nt++] = kt;
    }

    const size_t hoff = (size_t)h * S_LEN * HD;
    auto fetch = [&](int kt) {
        size_t gb = hoff + (size_t)(base + kt * 128) * HD;
        for (int f = tid; f < 1024; f += 256) {
            int r = f >> 3, c = f & 7;
            uint32_t so = r * 144 + c * 16;
            size_t go = gb + (size_t)r * HD + c * 8;
            cp16(KHI + so, g_kh + go);
            cp16(KLO + so, g_kl + go);
            cp16(VHI + so, g_vh + go);
        }
    };

    // prologue: Q plane + first K/V tile
    {
        size_t qoff = ((size_t)h * S_LEN + w * WSZ + q0) * HD;
        for (int f = tid; f < 1024; f += 256) {
            int r = f >> 3, c = f & 7;
            cp16(QHI + r * 144 + c * 16, g_q16 + qoff + (size_t)r * HD + c * 8);
        }
    }
    fetch(tiles[0]);
    asm volatile("cp.async.commit_group;" ::: "memory");

    float m0r = -1e30f, m1r = -1e30f, l0r = 0.f, l1r = 0.f;
    float o[8][4];
#pragma unroll
    for (int f = 0; f < 8; f++)
#pragma unroll
        for (int e = 0; e < 4; e++) o[f][e] = 0.f;

    const int r0 = Q0w + (lane >> 2);
    const int r1 = r0 + 8;

    for (int i = 0; i < nt; i++) {
        asm volatile("cp.async.wait_group 0;" ::: "memory");
        __syncthreads();

        if (i == 0) {
            // Closed-form pad tiles: s = -sum(q_scaled) (k = v = -1, all valid).
            const __half* qh = (const __half*)smc;
            int lr0 = warp * 16 + (lane >> 2);
            float qs0 = 0.f, qs1 = 0.f;
#pragma unroll
            for (int d = 0; d < HD; d++) {
                qs0 += __half2float(qh[lr0 * RS + d]);
                qs1 += __half2float(qh[(lr0 + 8) * RS + d]);
            }
            if (npad) {
                float s0 = -qs0, s1 = -qs1;
                float nm0 = fmaxf(m0r, s0), nm1 = fmaxf(m1r, s1);
                float cr0 = ex2(m0r - nm0), cr1 = ex2(m1r - nm1);
                m0r = nm0; m1r = nm1;
                float p0 = ex2(s0 - nm0) * (128.f * npad);
                float p1 = ex2(s1 - nm1) * (128.f * npad);
                l0r = l0r * cr0 + p0;
                l1r = l1r * cr1 + p1;
#pragma unroll
                for (int f = 0; f < 8; f++) {
                    o[f][0] = o[f][0] * cr0 - p0;
                    o[f][1] = o[f][1] * cr0 - p0;
                    o[f][2] = o[f][2] * cr1 - p1;
                    o[f][3] = o[f][3] * cr1 - p1;
                }
            }
        }

        const int kt = tiles[i];
        const int c0 = kt * 128;
        const bool relevant = (c0 + 127 >= Q0w) && (c0 <= Q0w + 1039);

        if (relevant) {
            // ---- S = Q K^T (fp16 2-pass: Q·Kh + Q·Kl) ----
            float sS[16][4];
#pragma unroll
            for (int f = 0; f < 16; f++)
#pragma unroll
                for (int e = 0; e < 4; e++) sS[f][e] = 0.f;

#pragma unroll
            for (int s = 0; s < 4; s++) {
                uint32_t a0, a1, a2, a3;
                ldsm4(a0, a1, a2, a3, QHI + a_lane + s * 32);
#pragma unroll
                for (int p = 0; p < 8; p++) {
                    uint32_t bh0, bh1, bh2, bh3, bl0, bl1, bl2, bl3;
                    ldsm4(bh0, bh1, bh2, bh3, KHI + kb_lane + p * 2304 + s * 32);
                    ldsm4(bl0, bl1, bl2, bl3, KLO + kb_lane + p * 2304 + s * 32);
                    mma_f16(sS[2*p],   a0, a1, a2, a3, bh0, bh2);
                    mma_f16(sS[2*p+1], a0, a1, a2, a3, bh1, bh3);
                    mma_f16(sS[2*p],   a0, a1, a2, a3, bl0, bl2);
                    mma_f16(sS[2*p+1], a0, a1, a2, a3, bl1, bl3);
                }
            }

            const bool needmask = !((c0 >= Q0w + 15) && (c0 + 127 <= Q0w + 1024));
            if (needmask) {
#pragma unroll
                for (int f = 0; f < 16; f++) {
                    int c = c0 + f * 8 + (lane & 3) * 2;
#pragma unroll
                    for (int e = 0; e < 2; e++) {
                        int cc = c + e;
                        if (!(cc >= r0 && cc <= r0 + 1024)) sS[f][e]     = -1e30f;
                        if (!(cc >= r1 && cc <= r1 + 1024)) sS[f][2 + e] = -1e30f;
                    }
                }
            }

            float tm0 = -1e30f, tm1 = -1e30f;
#pragma unroll
            for (int f = 0; f < 16; f++) {
                tm0 = fmaxf(tm0, fmaxf(sS[f][0], sS[f][1]));
                tm1 = fmaxf(tm1, fmaxf(sS[f][2], sS[f][3]));
            }
            tm0 = fmaxf(tm0, __shfl_xor_sync(0xffffffffu, tm0, 1));
            tm0 = fmaxf(tm0, __shfl_xor_sync(0xffffffffu, tm0, 2));
            tm1 = fmaxf(tm1, __shfl_xor_sync(0xffffffffu, tm1, 1));
            tm1 = fmaxf(tm1, __shfl_xor_sync(0xffffffffu, tm1, 2));
            float nm0 = fmaxf(m0r, tm0), nm1 = fmaxf(m1r, tm1);
            float cr0 = ex2(m0r - nm0), cr1 = ex2(m1r - nm1);
            m0r = nm0; m1r = nm1;
#pragma unroll
            for (int f = 0; f < 8; f++) {
                o[f][0] *= cr0; o[f][1] *= cr0;
                o[f][2] *= cr1; o[f][3] *= cr1;
            }
            float la0 = 0.f, la1 = 0.f;

            // ---- P V (exp2 fused, fp16 single pass) ----
#pragma unroll
            for (int s2 = 0; s2 < 8; s2++) {
                int f0 = 2 * s2, f1 = f0 + 1;
                float p00 = ex2(sS[f0][0] - m0r), p01 = ex2(sS[f0][1] - m0r);
                float p02 = ex2(sS[f0][2] - m1r), p03 = ex2(sS[f0][3] - m1r);
                float p10 = ex2(sS[f1][0] - m0r), p11 = ex2(sS[f1][1] - m0r);
                float p12 = ex2(sS[f1][2] - m1r), p13 = ex2(sS[f1][3] - m1r);
                la0 += p00 + p01 + p10 + p11;
                la1 += p02 + p03 + p12 + p13;
                uint32_t ah0 = pack_h2(p00, p01);
                uint32_t ah1 = pack_h2(p02, p03);
                uint32_t ah2 = pack_h2(p10, p11);
                uint32_t ah3 = pack_h2(p12, p13);
#pragma unroll
                for (int q = 0; q < 4; q++) {
                    uint32_t bh0, bh1, bh2, bh3;
                    ldsm4t(bh0, bh1, bh2, bh3, VHI + vb_lane + s2 * 2304 + q * 32);
                    mma_f16(o[2*q],   ah0, ah1, ah2, ah3, bh0, bh2);
                    mma_f16(o[2*q+1], ah0, ah1, ah2, ah3, bh1, bh3);
                }
            }
            la0 += __shfl_xor_sync(0xffffffffu, la0, 1);
            la0 += __shfl_xor_sync(0xffffffffu, la0, 2);
            la1 += __shfl_xor_sync(0xffffffffu, la1, 1);
            la1 += __shfl_xor_sync(0xffffffffu, la1, 2);
            l0r = l0r * cr0 + la0;
            l1r = l1r * cr1 + la1;
        }

        if (i + 1 < nt) {
            __syncthreads();               // all warps done reading this tile
            fetch(tiles[i + 1]);
            asm volatile("cp.async.commit_group;" ::: "memory");
        }
    }

    // normalize + store att as single fp16 plane [s][e]
    const float i0 = 1.f / l0r, i1 = 1.f / l1r;
    const int sg0 = w * WSZ + q0 + warp * 16 + (lane >> 2);
    const int e0  = h * HD + (lane & 3) * 2;
    size_t o0 = (size_t)sg0 * E_DIM + e0;
    size_t o1 = o0 + 8 * E_DIM;
#pragma unroll
    for (int f = 0; f < 8; f++) {
        *(uint32_t*)(g_a16 + o0 + f * 8) = pack_h2(o[f][0] * i0, o[f][1] * i0);
        *(uint32_t*)(g_a16 + o1 + f * 8) = pack_h2(o[f][2] * i1, o[f][3] * i1);
    }
}

// ---------------------------------------------------------------------------
extern "C" void kernel_launch(void* const* d_in, const int* in_sizes, int n_in,
                              void* d_out, int out_size)
{
    const float* x  = (const float*)d_in[0];
    const float* wq = (const float*)d_in[1];
    const float* bq = (const float*)d_in[2];
    const float* wk = (const float*)d_in[3];
    const float* bk = (const float*)d_in[4];
    const float* wv = (const float*)d_in[5];
    const float* bv = (const float*)d_in[6];
    const float* wo = (const float*)d_in[7];
    const float* bo = (const float*)d_in[8];
    float* out = (float*)d_out;

    const int gsm2 = 4 * GST2;          // 73728
    const int gsm1 = 4 * GST1;          // 81920
    cudaFuncSetAttribute(gemm_qk_kernel, cudaFuncAttributeMaxDynamicSharedMemorySize, gsm2);
    cudaFuncSetAttribute(gemm_v_kernel,  cudaFuncAttributeMaxDynamicSharedMemorySize, gsm1);
    cudaFuncSetAttribute(gemm_out_kernel, cudaFuncAttributeMaxDynamicSharedMemorySize, gsm1);
    const int asm_b = 4 * REG;          // 73728 -> 2 CTAs/SM
    cudaFuncSetAttribute(attn_kernel, cudaFuncAttributeMaxDynamicSharedMemorySize, asm_b);

    presplit_kernel<<<8192, 256>>>((const float4*)x, (const float4*)wq, (const float4*)wk,
                                   (const float4*)wv, (const float4*)wo);

    dim3 gqk(E_DIM / 128, S_LEN / 128, 2);
    gemm_qk_kernel<<<gqk, 256, gsm2>>>(bq, bk);
    dim3 gg(E_DIM / 128, S_LEN / 128);
    gemm_v_kernel<<<gg, 256, gsm1>>>(bv);

    dim3 ga(4, 8, 16);
    attn_kernel<<<ga, 256, asm_b>>>();

    gemm_out_kernel<<<gg, 256, gsm1>>>(bo, out);
}